// round 1
// baseline (speedup 1.0000x reference)
#include <cuda_runtime.h>
#include <math.h>

#define TOK   100352          // B*H*W tokens
#define CC    192
#define NHEAD 6
#define HDIM  32
#define NWIN  2048            // B * 64 windows
#define HIDN  768

// Scratch (allocation-free rule: __device__ globals)
__device__ float g_xn [TOK * CC];        // LN1 output, window order
__device__ float g_qkv[TOK * 3 * CC];    // qkv, window order
__device__ float g_att[TOK * CC];        // attention output, window order
__device__ float g_xr [TOK * CC];        // residual branch, token order
__device__ float g_h  [TOK * CC];        // LN2 output, token order
__device__ float g_h1 [TOK * HIDN];      // fc1+gelu output, token order

// Map a window-order row (win*49+n) to its token index in (B, 56, 56).
// shifted[hh,ww] = x[(hh+3)%56, (ww+3)%56]; same map applies for write-back.
__device__ __forceinline__ int win_row_to_token(int row) {
    int win = row / 49, n = row % 49;
    int b   = win >> 6, wij = win & 63;
    int wi  = wij >> 3, wj  = wij & 7;
    int hh  = wi * 7 + n / 7;
    int ww  = wj * 7 + n % 7;
    int h = hh + 3; if (h >= 56) h -= 56;
    int w = ww + 3; if (w >= 56) w -= 56;
    return b * 3136 + h * 56 + w;
}

// LayerNorm over C=192, one warp per row. permute=1: row is window-order,
// source token is permuted (fused shift + window partition + LN1).
__global__ void ln_kernel(const float* __restrict__ x, const float* __restrict__ g,
                          const float* __restrict__ bta, float* __restrict__ out,
                          int permute)
{
    int row  = blockIdx.x * 8 + threadIdx.y;
    int lane = threadIdx.x;
    int src  = permute ? win_row_to_token(row) : row;
    const float* xp = x + (size_t)src * CC;
    float v[6];
    float s = 0.f, s2 = 0.f;
#pragma unroll
    for (int i = 0; i < 6; i++) {
        v[i] = xp[i * 32 + lane];
        s += v[i]; s2 += v[i] * v[i];
    }
#pragma unroll
    for (int o = 16; o; o >>= 1) {
        s  += __shfl_xor_sync(0xffffffffu, s, o);
        s2 += __shfl_xor_sync(0xffffffffu, s2, o);
    }
    float mu  = s * (1.f / 192.f);
    float var = s2 * (1.f / 192.f) - mu * mu;
    float inv = rsqrtf(var + 1e-5f);
    float* op = out + (size_t)row * CC;
#pragma unroll
    for (int i = 0; i < 6; i++) {
        int c = i * 32 + lane;
        op[c] = (v[i] - mu) * inv * g[c] + bta[c];
    }
}

// Tiled fp32 GEMM: C[M,N] = A[M,K] @ B[K,N] + bias, 64x64 tile, BK=16,
// 256 threads, 4x4 register tile per thread.
// EPI: 0 = bias only; 1 = bias + permuted write (window->token order);
//      2 = bias + exact GELU; 3 = bias + residual add.
template<int EPI>
__global__ void sgemm64(const float* __restrict__ A, const float* __restrict__ Bw,
                        const float* __restrict__ bias, float* __restrict__ Cout,
                        int Nn, int K, const float* __restrict__ resid)
{
    __shared__ float As[16][65];   // pad to break STS bank conflicts on transpose
    __shared__ float Bs[16][64];

    int tid = threadIdx.x;
    int tx = tid & 15, ty = tid >> 4;
    int bn = blockIdx.x * 64, bm = blockIdx.y * 64;

    float acc[4][4] = {};

    const int arow = tid >> 4;   // 0..15
    const int acol = tid & 15;   // 0..15 (k within chunk)
    const int brow = tid >> 6;   // 0..3
    const int bcol = tid & 63;

    for (int k0 = 0; k0 < K; k0 += 16) {
#pragma unroll
        for (int p = 0; p < 4; p++)
            As[acol][arow + p * 16] =
                A[(size_t)(bm + arow + p * 16) * K + k0 + acol];
#pragma unroll
        for (int p = 0; p < 4; p++)
            Bs[brow + p * 4][bcol] =
                Bw[(size_t)(k0 + brow + p * 4) * Nn + bn + bcol];
        __syncthreads();
#pragma unroll
        for (int k = 0; k < 16; k++) {
            float a0 = As[k][ty * 4 + 0];
            float a1 = As[k][ty * 4 + 1];
            float a2 = As[k][ty * 4 + 2];
            float a3 = As[k][ty * 4 + 3];
            float4 b4 = *(const float4*)&Bs[k][tx * 4];
            acc[0][0] += a0 * b4.x; acc[0][1] += a0 * b4.y; acc[0][2] += a0 * b4.z; acc[0][3] += a0 * b4.w;
            acc[1][0] += a1 * b4.x; acc[1][1] += a1 * b4.y; acc[1][2] += a1 * b4.z; acc[1][3] += a1 * b4.w;
            acc[2][0] += a2 * b4.x; acc[2][1] += a2 * b4.y; acc[2][2] += a2 * b4.z; acc[2][3] += a2 * b4.w;
            acc[3][0] += a3 * b4.x; acc[3][1] += a3 * b4.y; acc[3][2] += a3 * b4.z; acc[3][3] += a3 * b4.w;
        }
        __syncthreads();
    }

#pragma unroll
    for (int i = 0; i < 4; i++) {
        int row  = bm + ty * 4 + i;
        int orow = (EPI == 1) ? win_row_to_token(row) : row;
#pragma unroll
        for (int j = 0; j < 4; j++) {
            int col = bn + tx * 4 + j;
            float v = acc[i][j] + bias[col];
            if (EPI == 2) v = 0.5f * v * (1.f + erff(v * 0.70710678118654752f));
            if (EPI == 3) v += resid[(size_t)row * CC + col];
            Cout[(size_t)orow * Nn + col] = v;
        }
    }
}

// One CTA per (window, head): S = q k^T * scale + mask; softmax; O = S v.
__global__ void attn_kernel(const float* __restrict__ qkv,
                            const float* __restrict__ mask,
                            float* __restrict__ out)
{
    int win  = blockIdx.x / NHEAD;
    int head = blockIdx.x % NHEAD;
    __shared__ float qs[49 * 32], ks[49 * 32], vs[49 * 32];
    __shared__ float sm[49 * 50];

    const float* base = qkv + (size_t)win * 49 * (3 * CC);
    int tid = threadIdx.x;

    for (int i = tid; i < 49 * 32; i += 256) {
        int r = i / 32, c = i % 32;
        qs[i] = base[r * (3 * CC) +            head * 32 + c];
        ks[i] = base[r * (3 * CC) + CC       + head * 32 + c];
        vs[i] = base[r * (3 * CC) + 2 * CC   + head * 32 + c];
    }
    __syncthreads();

    const float* mk = mask + (size_t)(win & 63) * 49 * 49;
    const float scale = 0.17677669529663687f;  // 1/sqrt(32)
    for (int idx = tid; idx < 49 * 49; idx += 256) {
        int i = idx / 49, j = idx % 49;
        float acc = 0.f;
#pragma unroll
        for (int d = 0; d < 32; d++) acc += qs[i * 32 + d] * ks[j * 32 + d];
        sm[i * 50 + j] = acc * scale + mk[idx];
    }
    __syncthreads();

    int warp = tid >> 5, lane = tid & 31;
    for (int r = warp; r < 49; r += 8) {
        float v0 = sm[r * 50 + lane];                      // lane 0..31 < 49
        float v1 = (lane < 17) ? sm[r * 50 + lane + 32] : -1e30f;
        float m = fmaxf(v0, v1);
#pragma unroll
        for (int o = 16; o; o >>= 1) m = fmaxf(m, __shfl_xor_sync(0xffffffffu, m, o));
        float e0 = __expf(v0 - m);
        float e1 = (lane < 17) ? __expf(v1 - m) : 0.f;
        float s = e0 + e1;
#pragma unroll
        for (int o = 16; o; o >>= 1) s += __shfl_xor_sync(0xffffffffu, s, o);
        float inv = 1.f / s;
        sm[r * 50 + lane] = e0 * inv;
        if (lane < 17) sm[r * 50 + lane + 32] = e1 * inv;
    }
    __syncthreads();

    for (int idx = tid; idx < 49 * 32; idx += 256) {
        int i = idx / 32, d = idx % 32;
        float acc = 0.f;
#pragma unroll
        for (int j = 0; j < 49; j++) acc += sm[i * 50 + j] * vs[j * 32 + d];
        out[((size_t)win * 49 + i) * CC + head * 32 + d] = acc;
    }
}

extern "C" void kernel_launch(void* const* d_in, const int* in_sizes, int n_in,
                              void* d_out, int out_size)
{
    const float* x      = (const float*)d_in[0];
    const float* qkv_w  = (const float*)d_in[1];
    const float* qkv_b  = (const float*)d_in[2];
    const float* proj_w = (const float*)d_in[3];
    const float* proj_b = (const float*)d_in[4];
    const float* n1g    = (const float*)d_in[5];
    const float* n1b    = (const float*)d_in[6];
    const float* n2g    = (const float*)d_in[7];
    const float* n2b    = (const float*)d_in[8];
    const float* fc1w   = (const float*)d_in[9];
    const float* fc1b   = (const float*)d_in[10];
    const float* fc2w   = (const float*)d_in[11];
    const float* fc2b   = (const float*)d_in[12];
    const float* amask  = (const float*)d_in[13];
    float* out = (float*)d_out;

    float *xn, *qkv, *att, *xr, *h, *h1;
    cudaGetSymbolAddress((void**)&xn,  g_xn);
    cudaGetSymbolAddress((void**)&qkv, g_qkv);
    cudaGetSymbolAddress((void**)&att, g_att);
    cudaGetSymbolAddress((void**)&xr,  g_xr);
    cudaGetSymbolAddress((void**)&h,   g_h);
    cudaGetSymbolAddress((void**)&h1,  g_h1);

    dim3 lnb(32, 8);
    // 1) shift + window partition + LN1 (fused permutation)
    ln_kernel<<<TOK / 8, lnb>>>(x, n1g, n1b, xn, 1);
    // 2) QKV GEMM: (100352,192) @ (192,576)
    sgemm64<0><<<dim3(9, 1568), 256>>>(xn, qkv_w, qkv_b, qkv, 576, 192, nullptr);
    // 3) windowed attention per (window, head)
    attn_kernel<<<NWIN * NHEAD, 256>>>(qkv, amask, att);
    // 4) proj GEMM + un-window + un-shift write into xr (token order)
    sgemm64<1><<<dim3(3, 1568), 256>>>(att, proj_w, proj_b, xr, 192, 192, nullptr);
    // 5) LN2
    ln_kernel<<<TOK / 8, lnb>>>(xr, n2g, n2b, h, 0);
    // 6) fc1 + exact GELU
    sgemm64<2><<<dim3(12, 1568), 256>>>(h, fc1w, fc1b, h1, 768, 192, nullptr);
    // 7) fc2 + bias + residual -> d_out
    sgemm64<3><<<dim3(3, 1568), 256>>>(h1, fc2w, fc2b, out, 192, 768, xr);
}

// round 2
// speedup vs baseline: 1.7955x; 1.7955x over previous
#include <cuda_runtime.h>
#include <math.h>
#include <stdint.h>

#define TOK   100352          // B*H*W tokens
#define CC    192
#define NHEAD 6
#define HDIM  32
#define NWIN  2048            // B * 64 windows
#define HIDN  768

// Scratch (allocation-free rule: __device__ globals)
__device__ float g_xn [TOK * CC];        // LN1 output, window order
__device__ float g_qkv[TOK * 3 * CC];    // qkv, window order
__device__ float g_att[TOK * CC];        // attention output, window order
__device__ float g_xr [TOK * CC];        // residual branch, token order
__device__ float g_h  [TOK * CC];        // LN2 output, token order
__device__ float g_h1 [TOK * HIDN];      // fc1+gelu output, token order

// Map a window-order row (win*49+n) to its token index in (B, 56, 56).
__device__ __forceinline__ int win_row_to_token(int row) {
    int win = row / 49, n = row % 49;
    int b   = win >> 6, wij = win & 63;
    int wi  = wij >> 3, wj  = wij & 7;
    int hh  = wi * 7 + n / 7;
    int ww  = wj * 7 + n % 7;
    int h = hh + 3; if (h >= 56) h -= 56;
    int w = ww + 3; if (w >= 56) w -= 56;
    return b * 3136 + h * 56 + w;
}

__device__ __forceinline__ float tf32r(float x) {
    uint32_t u;
    asm("cvt.rna.tf32.f32 %0, %1;" : "=r"(u) : "f"(x));
    return __uint_as_float(u);
}

__device__ __forceinline__ void mma8(float* c, const uint32_t* a, const uint32_t* b) {
    asm volatile(
        "mma.sync.aligned.m16n8k8.row.col.f32.tf32.tf32.f32 "
        "{%0,%1,%2,%3},{%4,%5,%6,%7},{%8,%9},{%0,%1,%2,%3};"
        : "+f"(c[0]), "+f"(c[1]), "+f"(c[2]), "+f"(c[3])
        : "r"(a[0]), "r"(a[1]), "r"(a[2]), "r"(a[3]), "r"(b[0]), "r"(b[1]));
}

// LayerNorm over C=192, one warp per row.
__global__ void ln_kernel(const float* __restrict__ x, const float* __restrict__ g,
                          const float* __restrict__ bta, float* __restrict__ out,
                          int permute)
{
    int row  = blockIdx.x * 8 + threadIdx.y;
    int lane = threadIdx.x;
    int src  = permute ? win_row_to_token(row) : row;
    const float* xp = x + (size_t)src * CC;
    float v[6];
    float s = 0.f, s2 = 0.f;
#pragma unroll
    for (int i = 0; i < 6; i++) {
        v[i] = xp[i * 32 + lane];
        s += v[i]; s2 += v[i] * v[i];
    }
#pragma unroll
    for (int o = 16; o; o >>= 1) {
        s  += __shfl_xor_sync(0xffffffffu, s, o);
        s2 += __shfl_xor_sync(0xffffffffu, s2, o);
    }
    float mu  = s * (1.f / 192.f);
    float var = s2 * (1.f / 192.f) - mu * mu;
    float inv = rsqrtf(var + 1e-5f);
    float* op = out + (size_t)row * CC;
#pragma unroll
    for (int i = 0; i < 6; i++) {
        int c = i * 32 + lane;
        op[c] = (v[i] - mu) * inv * g[c] + bta[c];
    }
}

// TF32 tensor-core GEMM: C[M,N] = A[M,K] @ B[K,N] + bias.
// CTA tile 128x64, BK=32. 8 warps (4m x 2n), each warp 32x32 via 2x4 m16n8k8.
// EPI: 0 = bias; 1 = bias + permuted write; 2 = bias + exact GELU; 3 = bias + residual.
template<int EPI>
__global__ void __launch_bounds__(256)
tgemm(const float* __restrict__ A, const float* __restrict__ Bw,
      const float* __restrict__ bias, float* __restrict__ Cout,
      int Nn, int K, const float* __restrict__ resid)
{
    __shared__ float As[128 * 36];   // stride 36: frag banks (4g+q) distinct
    __shared__ float Bs[32 * 72];    // stride 72: frag banks (8q+g) distinct

    const int tid  = threadIdx.x;
    const int warp = tid >> 5, lane = tid & 31;
    const int wm = warp >> 1, wn = warp & 1;          // 4x2 warp grid
    const int bm = blockIdx.y * 128, bn = blockIdx.x * 64;
    const int gid = lane >> 2, qid = lane & 3;

    float acc[2][4][4] = {};

    const int ar = tid >> 3, ac4 = (tid & 7) * 4;     // A loader: 32 rows x 8 f4
    const int br = tid >> 4, bc4 = (tid & 15) * 4;    // B loader: 16 rows x 16 f4

    for (int k0 = 0; k0 < K; k0 += 32) {
#pragma unroll
        for (int p = 0; p < 4; p++) {
            float4 v = *(const float4*)&A[(size_t)(bm + ar + p * 32) * K + k0 + ac4];
            v.x = tf32r(v.x); v.y = tf32r(v.y); v.z = tf32r(v.z); v.w = tf32r(v.w);
            *(float4*)&As[(ar + p * 32) * 36 + ac4] = v;
        }
#pragma unroll
        for (int p = 0; p < 2; p++) {
            float4 v = *(const float4*)&Bw[(size_t)(k0 + br + p * 16) * Nn + bn + bc4];
            v.x = tf32r(v.x); v.y = tf32r(v.y); v.z = tf32r(v.z); v.w = tf32r(v.w);
            *(float4*)&Bs[(br + p * 16) * 72 + bc4] = v;
        }
        __syncthreads();

#pragma unroll
        for (int kk = 0; kk < 32; kk += 8) {
            uint32_t af[2][4], bf[4][2];
#pragma unroll
            for (int mt = 0; mt < 2; mt++) {
                int mb = wm * 32 + mt * 16;
                af[mt][0] = __float_as_uint(As[(mb + gid    ) * 36 + kk + qid    ]);
                af[mt][1] = __float_as_uint(As[(mb + gid + 8) * 36 + kk + qid    ]);
                af[mt][2] = __float_as_uint(As[(mb + gid    ) * 36 + kk + qid + 4]);
                af[mt][3] = __float_as_uint(As[(mb + gid + 8) * 36 + kk + qid + 4]);
            }
#pragma unroll
            for (int nt = 0; nt < 4; nt++) {
                int nb = wn * 32 + nt * 8;
                bf[nt][0] = __float_as_uint(Bs[(kk + qid    ) * 72 + nb + gid]);
                bf[nt][1] = __float_as_uint(Bs[(kk + qid + 4) * 72 + nb + gid]);
            }
#pragma unroll
            for (int mt = 0; mt < 2; mt++)
#pragma unroll
                for (int nt = 0; nt < 4; nt++)
                    mma8(acc[mt][nt], af[mt], bf[nt]);
        }
        __syncthreads();
    }

    // Epilogue. c0:(g,2q) c1:(g,2q+1) c2:(g+8,2q) c3:(g+8,2q+1)
#pragma unroll
    for (int mt = 0; mt < 2; mt++) {
#pragma unroll
        for (int half = 0; half < 2; half++) {
            int row  = bm + wm * 32 + mt * 16 + gid + half * 8;
            int orow = (EPI == 1) ? win_row_to_token(row) : row;
#pragma unroll
            for (int nt = 0; nt < 4; nt++) {
                int col = bn + wn * 32 + nt * 8 + qid * 2;
                float v0 = acc[mt][nt][half * 2 + 0] + bias[col];
                float v1 = acc[mt][nt][half * 2 + 1] + bias[col + 1];
                if (EPI == 2) {
                    v0 = 0.5f * v0 * (1.f + erff(v0 * 0.70710678118654752f));
                    v1 = 0.5f * v1 * (1.f + erff(v1 * 0.70710678118654752f));
                }
                if (EPI == 3) {
                    v0 += resid[(size_t)row * CC + col];
                    v1 += resid[(size_t)row * CC + col + 1];
                }
                float2 o = make_float2(v0, v1);
                *(float2*)&Cout[(size_t)orow * Nn + col] = o;
            }
        }
    }
}

// One CTA per (window, head): S = q k^T * scale + mask; softmax; O = S v.
__global__ void attn_kernel(const float* __restrict__ qkv,
                            const float* __restrict__ mask,
                            float* __restrict__ out)
{
    int win  = blockIdx.x / NHEAD;
    int head = blockIdx.x % NHEAD;
    __shared__ float qs[49 * 32], ks[49 * 32], vs[49 * 32];
    __shared__ float sm[49 * 50];

    const float* base = qkv + (size_t)win * 49 * (3 * CC);
    int tid = threadIdx.x;

    for (int i = tid; i < 49 * 32; i += 256) {
        int r = i / 32, c = i % 32;
        qs[i] = base[r * (3 * CC) +            head * 32 + c];
        ks[i] = base[r * (3 * CC) + CC       + head * 32 + c];
        vs[i] = base[r * (3 * CC) + 2 * CC   + head * 32 + c];
    }
    __syncthreads();

    const float* mk = mask + (size_t)(win & 63) * 49 * 49;
    const float scale = 0.17677669529663687f;  // 1/sqrt(32)
    for (int idx = tid; idx < 49 * 49; idx += 256) {
        int i = idx / 49, j = idx % 49;
        float acc = 0.f;
#pragma unroll
        for (int d = 0; d < 32; d++) acc += qs[i * 32 + d] * ks[j * 32 + d];
        sm[i * 50 + j] = acc * scale + mk[idx];
    }
    __syncthreads();

    int warp = tid >> 5, lane = tid & 31;
    for (int r = warp; r < 49; r += 8) {
        float v0 = sm[r * 50 + lane];
        float v1 = (lane < 17) ? sm[r * 50 + lane + 32] : -1e30f;
        float m = fmaxf(v0, v1);
#pragma unroll
        for (int o = 16; o; o >>= 1) m = fmaxf(m, __shfl_xor_sync(0xffffffffu, m, o));
        float e0 = __expf(v0 - m);
        float e1 = (lane < 17) ? __expf(v1 - m) : 0.f;
        float s = e0 + e1;
#pragma unroll
        for (int o = 16; o; o >>= 1) s += __shfl_xor_sync(0xffffffffu, s, o);
        float inv = 1.f / s;
        sm[r * 50 + lane] = e0 * inv;
        if (lane < 17) sm[r * 50 + lane + 32] = e1 * inv;
    }
    __syncthreads();

    for (int idx = tid; idx < 49 * 32; idx += 256) {
        int i = idx / 32, d = idx % 32;
        float acc = 0.f;
#pragma unroll
        for (int j = 0; j < 49; j++) acc += sm[i * 50 + j] * vs[j * 32 + d];
        out[((size_t)win * 49 + i) * CC + head * 32 + d] = acc;
    }
}

extern "C" void kernel_launch(void* const* d_in, const int* in_sizes, int n_in,
                              void* d_out, int out_size)
{
    const float* x      = (const float*)d_in[0];
    const float* qkv_w  = (const float*)d_in[1];
    const float* qkv_b  = (const float*)d_in[2];
    const float* proj_w = (const float*)d_in[3];
    const float* proj_b = (const float*)d_in[4];
    const float* n1g    = (const float*)d_in[5];
    const float* n1b    = (const float*)d_in[6];
    const float* n2g    = (const float*)d_in[7];
    const float* n2b    = (const float*)d_in[8];
    const float* fc1w   = (const float*)d_in[9];
    const float* fc1b   = (const float*)d_in[10];
    const float* fc2w   = (const float*)d_in[11];
    const float* fc2b   = (const float*)d_in[12];
    const float* amask  = (const float*)d_in[13];
    float* out = (float*)d_out;

    float *xn, *qkv, *att, *xr, *h, *h1;
    cudaGetSymbolAddress((void**)&xn,  g_xn);
    cudaGetSymbolAddress((void**)&qkv, g_qkv);
    cudaGetSymbolAddress((void**)&att, g_att);
    cudaGetSymbolAddress((void**)&xr,  g_xr);
    cudaGetSymbolAddress((void**)&h,   g_h);
    cudaGetSymbolAddress((void**)&h1,  g_h1);

    dim3 lnb(32, 8);
    // 1) shift + window partition + LN1 (fused permutation)
    ln_kernel<<<TOK / 8, lnb>>>(x, n1g, n1b, xn, 1);
    // 2) QKV GEMM: (100352,192) @ (192,576)
    tgemm<0><<<dim3(9, 784), 256>>>(xn, qkv_w, qkv_b, qkv, 576, 192, nullptr);
    // 3) windowed attention per (window, head)
    attn_kernel<<<NWIN * NHEAD, 256>>>(qkv, amask, att);
    // 4) proj GEMM + un-window + un-shift write into xr (token order)
    tgemm<1><<<dim3(3, 784), 256>>>(att, proj_w, proj_b, xr, 192, 192, nullptr);
    // 5) LN2
    ln_kernel<<<TOK / 8, lnb>>>(xr, n2g, n2b, h, 0);
    // 6) fc1 + exact GELU
    tgemm<2><<<dim3(12, 784), 256>>>(h, fc1w, fc1b, h1, 768, 192, nullptr);
    // 7) fc2 + bias + residual -> d_out
    tgemm<3><<<dim3(3, 784), 256>>>(h1, fc2w, fc2b, out, 192, 768, xr);
}

// round 3
// speedup vs baseline: 2.1454x; 1.1948x over previous
#include <cuda_runtime.h>
#include <math.h>
#include <stdint.h>

#define TOK   100352          // B*H*W tokens
#define CC    192
#define NHEAD 6
#define HDIM  32
#define NWIN  2048            // B * 64 windows
#define HIDN  768

// Scratch (allocation-free rule: __device__ globals)
__device__ float g_xn [TOK * CC];        // LN1 output (tf32-rounded), window order
__device__ float g_qkv[TOK * 3 * CC];    // qkv, window order (fp32)
__device__ float g_att[TOK * CC];        // attention output (tf32-rounded), window order
__device__ float g_xr [TOK * CC];        // residual branch, token order (fp32)
__device__ float g_h  [TOK * CC];        // LN2 output (tf32-rounded), token order
__device__ float g_h1 [TOK * HIDN];      // fc1+gelu output (tf32-rounded)
__device__ float g_w  [442368];          // tf32-rounded weights (qkv|proj|fc1|fc2)

#define OFF_QKVW 0
#define OFF_PROJW 110592
#define OFF_FC1W  147456
#define OFF_FC2W  294912

__device__ __forceinline__ int win_row_to_token(int row) {
    int win = row / 49, n = row % 49;
    int b   = win >> 6, wij = win & 63;
    int wi  = wij >> 3, wj  = wij & 7;
    int hh  = wi * 7 + n / 7;
    int ww  = wj * 7 + n % 7;
    int h = hh + 3; if (h >= 56) h -= 56;
    int w = ww + 3; if (w >= 56) w -= 56;
    return b * 3136 + h * 56 + w;
}

__device__ __forceinline__ float tf32r(float x) {
    uint32_t u;
    asm("cvt.rna.tf32.f32 %0, %1;" : "=r"(u) : "f"(x));
    return __uint_as_float(u);
}

__device__ __forceinline__ void mma8(float* c, const float4 a, const float bx, const float by) {
    asm volatile(
        "mma.sync.aligned.m16n8k8.row.col.f32.tf32.tf32.f32 "
        "{%0,%1,%2,%3},{%4,%5,%6,%7},{%8,%9},{%0,%1,%2,%3};"
        : "+f"(c[0]), "+f"(c[1]), "+f"(c[2]), "+f"(c[3])
        : "r"(__float_as_uint(a.x)), "r"(__float_as_uint(a.y)),
          "r"(__float_as_uint(a.z)), "r"(__float_as_uint(a.w)),
          "r"(__float_as_uint(bx)), "r"(__float_as_uint(by)));
}

// Round weights to tf32 once.
__global__ void round_w(const float* __restrict__ w, float* __restrict__ o, int n) {
    int i = blockIdx.x * 256 + threadIdx.x;
    if (i < n) o[i] = tf32r(w[i]);
}

// LayerNorm over C=192, one warp per row; output tf32-rounded (feeds GEMM A).
__global__ void ln_kernel(const float* __restrict__ x, const float* __restrict__ g,
                          const float* __restrict__ bta, float* __restrict__ out,
                          int permute)
{
    int row  = blockIdx.x * 8 + threadIdx.y;
    int lane = threadIdx.x;
    int src  = permute ? win_row_to_token(row) : row;
    const float* xp = x + (size_t)src * CC;
    float v[6];
    float s = 0.f, s2 = 0.f;
#pragma unroll
    for (int i = 0; i < 6; i++) {
        v[i] = xp[i * 32 + lane];
        s += v[i]; s2 += v[i] * v[i];
    }
#pragma unroll
    for (int o = 16; o; o >>= 1) {
        s  += __shfl_xor_sync(0xffffffffu, s, o);
        s2 += __shfl_xor_sync(0xffffffffu, s2, o);
    }
    float mu  = s * (1.f / 192.f);
    float var = s2 * (1.f / 192.f) - mu * mu;
    float inv = rsqrtf(var + 1e-5f);
    float* op = out + (size_t)row * CC;
#pragma unroll
    for (int i = 0; i < 6; i++) {
        int c = i * 32 + lane;
        op[c] = tf32r((v[i] - mu) * inv * g[c] + bta[c]);
    }
}

// TF32 tensor-core GEMM, fragment-layout smem, double buffered.
// CTA tile 128x64, BK=32, 8 warps (4m x 2n), warp tile 32x32 (2x4 m16n8k8).
// Inputs are pre-rounded to tf32. EPI: 0 bias; 1 bias+permuted write;
// 2 bias+GELU (rounded out); 3 bias+residual.
template<int EPI>
__global__ void __launch_bounds__(256)
tgemm(const float* __restrict__ A, const float* __restrict__ Bw,
      const float* __restrict__ bias, float* __restrict__ Cout,
      int Nn, int K, const float* __restrict__ resid)
{
    // fragment order: As[stage][kchunk][mrow16][ (lane^kc)*4 + (i+2h) ]
    //                 Bs[stage][kchunk][wn][sg][ (lane^kc)*4 + ((nt&1)*2+h) ]
    __shared__ float As[2][4][8][128];
    __shared__ float Bs[2][4][2][2][128];

    const int tid  = threadIdx.x;
    const int warp = tid >> 5, lane = tid & 31;
    const int wm = warp >> 1, wn = warp & 1;
    const int bm = blockIdx.y * 128, bn = blockIdx.x * 64;
    const int gid = lane >> 2, qid = lane & 3;

    float acc[2][4][4] = {};

    // A loader: row ar (+p*32), cols ac4..ac4+3
    const int ar = tid >> 3, ac4 = (tid & 7) * 4;
    const int a_kc = ac4 >> 3, a_h = (ac4 >> 2) & 1;
    // B loader: row br (+p*16), cols bc4..bc4+3
    const int br = tid >> 4, bc4 = (tid & 15) * 4;
    const int b_wn = bc4 >> 5, b_nt = (bc4 >> 3) & 3, b_g0 = bc4 & 7;
    const int b_sg = b_nt >> 1;

    float4 areg[4], breg[2];
    const int nk = K >> 5;

    auto ldg = [&](int kb) {
        int k0 = kb << 5;
#pragma unroll
        for (int p = 0; p < 4; p++)
            areg[p] = *(const float4*)&A[(size_t)(bm + ar + p * 32) * K + k0 + ac4];
#pragma unroll
        for (int p = 0; p < 2; p++)
            breg[p] = *(const float4*)&Bw[(size_t)(k0 + br + p * 16) * Nn + bn + bc4];
    };
    auto sts = [&](int st) {
#pragma unroll
        for (int p = 0; p < 4; p++) {
            int m = ar + p * 32;
            int mrow = m >> 4, ii = (m >> 3) & 1, g = m & 7;
            int slot = ii + 2 * a_h;
            float* base = &As[st][a_kc][mrow][0];
            base[(((g * 4 + 0) ^ a_kc) << 2) + slot] = areg[p].x;
            base[(((g * 4 + 1) ^ a_kc) << 2) + slot] = areg[p].y;
            base[(((g * 4 + 2) ^ a_kc) << 2) + slot] = areg[p].z;
            base[(((g * 4 + 3) ^ a_kc) << 2) + slot] = areg[p].w;
        }
#pragma unroll
        for (int p = 0; p < 2; p++) {
            int k = br + p * 16;
            int kc = k >> 3, q = k & 3, h = (k >> 2) & 1;
            int idx = (b_nt & 1) * 2 + h;
            float* base = &Bs[st][kc][b_wn][b_sg][0];
            base[((((b_g0 + 0) * 4 + q) ^ kc) << 2) + idx] = breg[p].x;
            base[((((b_g0 + 1) * 4 + q) ^ kc) << 2) + idx] = breg[p].y;
            base[((((b_g0 + 2) * 4 + q) ^ kc) << 2) + idx] = breg[p].z;
            base[((((b_g0 + 3) * 4 + q) ^ kc) << 2) + idx] = breg[p].w;
        }
    };

    ldg(0);
    sts(0);
    __syncthreads();

    for (int kb = 0; kb < nk; kb++) {
        int st = kb & 1;
        if (kb + 1 < nk) ldg(kb + 1);
#pragma unroll
        for (int kc = 0; kc < 4; kc++) {
            int xl = (lane ^ kc) << 2;
            float4 fa0 = *(const float4*)&As[st][kc][wm * 2 + 0][xl];
            float4 fa1 = *(const float4*)&As[st][kc][wm * 2 + 1][xl];
            float4 fb0 = *(const float4*)&Bs[st][kc][wn][0][xl];
            float4 fb1 = *(const float4*)&Bs[st][kc][wn][1][xl];
            mma8(acc[0][0], fa0, fb0.x, fb0.y);
            mma8(acc[0][1], fa0, fb0.z, fb0.w);
            mma8(acc[0][2], fa0, fb1.x, fb1.y);
            mma8(acc[0][3], fa0, fb1.z, fb1.w);
            mma8(acc[1][0], fa1, fb0.x, fb0.y);
            mma8(acc[1][1], fa1, fb0.z, fb0.w);
            mma8(acc[1][2], fa1, fb1.x, fb1.y);
            mma8(acc[1][3], fa1, fb1.z, fb1.w);
        }
        if (kb + 1 < nk) {
            sts((kb + 1) & 1);
            __syncthreads();
        }
    }

    // Epilogue. c0:(g,2q) c1:(g,2q+1) c2:(g+8,2q) c3:(g+8,2q+1)
#pragma unroll
    for (int mt = 0; mt < 2; mt++) {
#pragma unroll
        for (int half = 0; half < 2; half++) {
            int row  = bm + wm * 32 + mt * 16 + gid + half * 8;
            int orow = (EPI == 1) ? win_row_to_token(row) : row;
#pragma unroll
            for (int nt = 0; nt < 4; nt++) {
                int col = bn + wn * 32 + nt * 8 + qid * 2;
                float v0 = acc[mt][nt][half * 2 + 0] + bias[col];
                float v1 = acc[mt][nt][half * 2 + 1] + bias[col + 1];
                if (EPI == 2) {
                    v0 = tf32r(0.5f * v0 * (1.f + erff(v0 * 0.70710678118654752f)));
                    v1 = tf32r(0.5f * v1 * (1.f + erff(v1 * 0.70710678118654752f)));
                }
                if (EPI == 3) {
                    v0 += resid[(size_t)row * CC + col];
                    v1 += resid[(size_t)row * CC + col + 1];
                }
                float2 o = make_float2(v0, v1);
                *(float2*)&Cout[(size_t)orow * Nn + col] = o;
            }
        }
    }
}

// One CTA per (window, head): S = q k^T * scale + mask; softmax; O = S v.
__global__ void __launch_bounds__(256) attn_kernel(const float* __restrict__ qkv,
                            const float* __restrict__ mask,
                            float* __restrict__ out)
{
    int win  = blockIdx.x / NHEAD;
    int head = blockIdx.x % NHEAD;
    __shared__ float qs[49 * 36], ks[49 * 36], vs[49 * 36];  // pad 36: bank spread
    __shared__ float sm[49 * 50];

    const float* base = qkv + (size_t)win * 49 * (3 * CC);
    int tid = threadIdx.x;
    int warp = tid >> 5, lane = tid & 31;

    for (int t = tid; t < 49 * 32; t += 256) {
        int r = t >> 5, c = t & 31;
        qs[r * 36 + c] = base[r * (3 * CC) +          head * 32 + c];
        ks[r * 36 + c] = base[r * (3 * CC) + CC     + head * 32 + c];
        vs[r * 36 + c] = base[r * (3 * CC) + 2 * CC + head * 32 + c];
    }
    __syncthreads();

    const float* mk = mask + (size_t)(win & 63) * 49 * 49;
    const float scale = 0.17677669529663687f;  // 1/sqrt(32)

    for (int i = warp; i < 49; i += 8) {
        float4 q[8];
#pragma unroll
        for (int t = 0; t < 8; t++) q[t] = *(const float4*)&qs[i * 36 + t * 4];  // broadcast
        int j0 = lane, j1 = lane + 32;
        float acc0 = 0.f, acc1 = 0.f;
#pragma unroll
        for (int t = 0; t < 8; t++) {
            float4 k4 = *(const float4*)&ks[j0 * 36 + t * 4];
            acc0 += q[t].x * k4.x + q[t].y * k4.y + q[t].z * k4.z + q[t].w * k4.w;
        }
        if (j1 < 49) {
#pragma unroll
            for (int t = 0; t < 8; t++) {
                float4 k4 = *(const float4*)&ks[j1 * 36 + t * 4];
                acc1 += q[t].x * k4.x + q[t].y * k4.y + q[t].z * k4.z + q[t].w * k4.w;
            }
        }
        sm[i * 50 + j0] = acc0 * scale + mk[i * 49 + j0];
        if (j1 < 49) sm[i * 50 + j1] = acc1 * scale + mk[i * 49 + j1];
    }
    __syncthreads();

    for (int r = warp; r < 49; r += 8) {
        float v0 = sm[r * 50 + lane];
        float v1 = (lane < 17) ? sm[r * 50 + lane + 32] : -1e30f;
        float m = fmaxf(v0, v1);
#pragma unroll
        for (int o = 16; o; o >>= 1) m = fmaxf(m, __shfl_xor_sync(0xffffffffu, m, o));
        float e0 = __expf(v0 - m);
        float e1 = (lane < 17) ? __expf(v1 - m) : 0.f;
        float s = e0 + e1;
#pragma unroll
        for (int o = 16; o; o >>= 1) s += __shfl_xor_sync(0xffffffffu, s, o);
        float inv = 1.f / s;
        sm[r * 50 + lane] = e0 * inv;
        if (lane < 17) sm[r * 50 + lane + 32] = e1 * inv;
    }
    __syncthreads();

    for (int i = warp; i < 49; i += 8) {
        float acc = 0.f;
#pragma unroll 7
        for (int j = 0; j < 49; j++)
            acc += sm[i * 50 + j] * vs[j * 36 + lane];   // sm broadcast, vs coalesced
        out[((size_t)win * 49 + i) * CC + head * 32 + lane] = tf32r(acc);
    }
}

extern "C" void kernel_launch(void* const* d_in, const int* in_sizes, int n_in,
                              void* d_out, int out_size)
{
    const float* x      = (const float*)d_in[0];
    const float* qkv_w  = (const float*)d_in[1];
    const float* qkv_b  = (const float*)d_in[2];
    const float* proj_w = (const float*)d_in[3];
    const float* proj_b = (const float*)d_in[4];
    const float* n1g    = (const float*)d_in[5];
    const float* n1b    = (const float*)d_in[6];
    const float* n2g    = (const float*)d_in[7];
    const float* n2b    = (const float*)d_in[8];
    const float* fc1w   = (const float*)d_in[9];
    const float* fc1b   = (const float*)d_in[10];
    const float* fc2w   = (const float*)d_in[11];
    const float* fc2b   = (const float*)d_in[12];
    const float* amask  = (const float*)d_in[13];
    float* out = (float*)d_out;

    float *xn, *qkv, *att, *xr, *h, *h1, *w;
    cudaGetSymbolAddress((void**)&xn,  g_xn);
    cudaGetSymbolAddress((void**)&qkv, g_qkv);
    cudaGetSymbolAddress((void**)&att, g_att);
    cudaGetSymbolAddress((void**)&xr,  g_xr);
    cudaGetSymbolAddress((void**)&h,   g_h);
    cudaGetSymbolAddress((void**)&h1,  g_h1);
    cudaGetSymbolAddress((void**)&w,   g_w);

    // 0) pre-round weights to tf32
    round_w<<<(110592 + 255) / 256, 256>>>(qkv_w,  w + OFF_QKVW, 110592);
    round_w<<<(36864  + 255) / 256, 256>>>(proj_w, w + OFF_PROJW, 36864);
    round_w<<<(147456 + 255) / 256, 256>>>(fc1w,   w + OFF_FC1W, 147456);
    round_w<<<(147456 + 255) / 256, 256>>>(fc2w,   w + OFF_FC2W, 147456);

    dim3 lnb(32, 8);
    // 1) shift + window partition + LN1 (fused permutation), tf32-rounded out
    ln_kernel<<<TOK / 8, lnb>>>(x, n1g, n1b, xn, 1);
    // 2) QKV GEMM: (100352,192) @ (192,576)
    tgemm<0><<<dim3(9, 784), 256>>>(xn, w + OFF_QKVW, qkv_b, qkv, 576, 192, nullptr);
    // 3) windowed attention per (window, head), tf32-rounded out
    attn_kernel<<<NWIN * NHEAD, 256>>>(qkv, amask, att);
    // 4) proj GEMM + un-window + un-shift write into xr (token order)
    tgemm<1><<<dim3(3, 784), 256>>>(att, w + OFF_PROJW, proj_b, xr, 192, 192, nullptr);
    // 5) LN2, tf32-rounded out
    ln_kernel<<<TOK / 8, lnb>>>(xr, n2g, n2b, h, 0);
    // 6) fc1 + exact GELU, tf32-rounded out
    tgemm<2><<<dim3(12, 784), 256>>>(h, w + OFF_FC1W, fc1b, h1, 768, 192, nullptr);
    // 7) fc2 + bias + residual -> d_out
    tgemm<3><<<dim3(3, 784), 256>>>(h1, w + OFF_FC2W, fc2b, out, 192, 768, xr);
}

// round 4
// speedup vs baseline: 2.6303x; 1.2260x over previous
#include <cuda_runtime.h>
#include <math.h>
#include <stdint.h>

#define TOK   100352          // B*H*W tokens
#define CC    192
#define NHEAD 6
#define HDIM  32
#define NWIN  2048            // B * 64 windows
#define HIDN  768

// Scratch (allocation-free rule: __device__ globals)
__device__ float g_xn [TOK * CC];        // LN1 output (tf32-rounded), window order
__device__ float g_qkv[TOK * 3 * CC];    // qkv, window order (fp32)
__device__ float g_att[TOK * CC];        // attention output (tf32-rounded), window order
__device__ float g_xr [TOK * CC];        // residual branch, token order (fp32)
__device__ float g_h  [TOK * CC];        // LN2 output (tf32-rounded), token order
__device__ float g_h1 [TOK * HIDN];      // fc1+gelu output (tf32-rounded)
__device__ float g_w  [442368];          // tf32-rounded weights (qkv|proj|fc1|fc2)

#define OFF_QKVW 0
#define OFF_PROJW 110592
#define OFF_FC1W  147456
#define OFF_FC2W  294912

__device__ __forceinline__ int win_row_to_token(int row) {
    int win = row / 49, n = row % 49;
    int b   = win >> 6, wij = win & 63;
    int wi  = wij >> 3, wj  = wij & 7;
    int hh  = wi * 7 + n / 7;
    int ww  = wj * 7 + n % 7;
    int h = hh + 3; if (h >= 56) h -= 56;
    int w = ww + 3; if (w >= 56) w -= 56;
    return b * 3136 + h * 56 + w;
}

__device__ __forceinline__ float tf32r(float x) {
    uint32_t u;
    asm("cvt.rna.tf32.f32 %0, %1;" : "=r"(u) : "f"(x));
    return __uint_as_float(u);
}

__device__ __forceinline__ void mma8(float* c, const float4 a, const float bx, const float by) {
    asm volatile(
        "mma.sync.aligned.m16n8k8.row.col.f32.tf32.tf32.f32 "
        "{%0,%1,%2,%3},{%4,%5,%6,%7},{%8,%9},{%0,%1,%2,%3};"
        : "+f"(c[0]), "+f"(c[1]), "+f"(c[2]), "+f"(c[3])
        : "r"(__float_as_uint(a.x)), "r"(__float_as_uint(a.y)),
          "r"(__float_as_uint(a.z)), "r"(__float_as_uint(a.w)),
          "r"(__float_as_uint(bx)), "r"(__float_as_uint(by)));
}

__global__ void round_w(const float* __restrict__ w, float* __restrict__ o, int n) {
    int i = blockIdx.x * 256 + threadIdx.x;
    if (i < n) o[i] = tf32r(w[i]);
}

// LayerNorm over C=192, one warp per row; output tf32-rounded (feeds GEMM A).
__global__ void ln_kernel(const float* __restrict__ x, const float* __restrict__ g,
                          const float* __restrict__ bta, float* __restrict__ out,
                          int permute)
{
    int row  = blockIdx.x * 8 + threadIdx.y;
    int lane = threadIdx.x;
    int src  = permute ? win_row_to_token(row) : row;
    const float* xp = x + (size_t)src * CC;
    float v[6];
    float s = 0.f, s2 = 0.f;
#pragma unroll
    for (int i = 0; i < 6; i++) {
        v[i] = xp[i * 32 + lane];
        s += v[i]; s2 += v[i] * v[i];
    }
#pragma unroll
    for (int o = 16; o; o >>= 1) {
        s  += __shfl_xor_sync(0xffffffffu, s, o);
        s2 += __shfl_xor_sync(0xffffffffu, s2, o);
    }
    float mu  = s * (1.f / 192.f);
    float var = s2 * (1.f / 192.f) - mu * mu;
    float inv = rsqrtf(var + 1e-5f);
    float* op = out + (size_t)row * CC;
#pragma unroll
    for (int i = 0; i < 6; i++) {
        int c = i * 32 + lane;
        op[c] = tf32r((v[i] - mu) * inv * g[c] + bta[c]);
    }
}

// TF32 tensor-core GEMM, fragment-layout smem, double buffered.
// CTA tile 128x64, BK=32, 4 warps (2m x 2n), warp tile 64x32 (4x4 m16n8k8).
template<int EPI>
__global__ void __launch_bounds__(128)
tgemm(const float* __restrict__ A, const float* __restrict__ Bw,
      const float* __restrict__ bias, float* __restrict__ Cout,
      int Nn, int K, const float* __restrict__ resid)
{
    __shared__ float As[2][4][8][128];        // 32KB
    __shared__ float Bs[2][4][2][2][128];     // 16KB

    const int tid  = threadIdx.x;
    const int warp = tid >> 5, lane = tid & 31;
    const int wm = warp >> 1, wn = warp & 1;
    const int bm = blockIdx.y * 128, bn = blockIdx.x * 64;
    const int gid = lane >> 2, qid = lane & 3;

    float acc[4][4][4] = {};

    // A loader: 128 threads, 8 float4 each: row ar+p*16, cols ac4..ac4+3
    const int ar = tid >> 3, ac4 = (tid & 7) * 4;
    const int a_kc = ac4 >> 3, a_h = (ac4 >> 2) & 1;
    // B loader: 4 float4 each: row br+p*8, cols bc4..bc4+3
    const int br = tid >> 4, bc4 = (tid & 15) * 4;
    const int b_wn = bc4 >> 5, b_nt = (bc4 >> 3) & 3, b_g0 = bc4 & 7;
    const int b_sg = b_nt >> 1;

    float4 areg[8], breg[4];
    const int nk = K >> 5;

    auto ldg = [&](int kb) {
        int k0 = kb << 5;
#pragma unroll
        for (int p = 0; p < 8; p++)
            areg[p] = *(const float4*)&A[(size_t)(bm + ar + p * 16) * K + k0 + ac4];
#pragma unroll
        for (int p = 0; p < 4; p++)
            breg[p] = *(const float4*)&Bw[(size_t)(k0 + br + p * 8) * Nn + bn + bc4];
    };
    auto sts = [&](int st) {
#pragma unroll
        for (int p = 0; p < 8; p++) {
            int m = ar + p * 16;
            int mrow = m >> 4, ii = (m >> 3) & 1, g = m & 7;
            int slot = ii + 2 * a_h;
            float* base = &As[st][a_kc][mrow][0];
            base[(((g * 4 + 0) ^ a_kc) << 2) + slot] = areg[p].x;
            base[(((g * 4 + 1) ^ a_kc) << 2) + slot] = areg[p].y;
            base[(((g * 4 + 2) ^ a_kc) << 2) + slot] = areg[p].z;
            base[(((g * 4 + 3) ^ a_kc) << 2) + slot] = areg[p].w;
        }
#pragma unroll
        for (int p = 0; p < 4; p++) {
            int k = br + p * 8;
            int kc = k >> 3, q = k & 3, h = (k >> 2) & 1;
            int idx = (b_nt & 1) * 2 + h;
            float* base = &Bs[st][kc][b_wn][b_sg][0];
            base[((((b_g0 + 0) * 4 + q) ^ kc) << 2) + idx] = breg[p].x;
            base[((((b_g0 + 1) * 4 + q) ^ kc) << 2) + idx] = breg[p].y;
            base[((((b_g0 + 2) * 4 + q) ^ kc) << 2) + idx] = breg[p].z;
            base[((((b_g0 + 3) * 4 + q) ^ kc) << 2) + idx] = breg[p].w;
        }
    };

    ldg(0);
    sts(0);
    __syncthreads();

    for (int kb = 0; kb < nk; kb++) {
        int st = kb & 1;
        if (kb + 1 < nk) ldg(kb + 1);
#pragma unroll
        for (int kc = 0; kc < 4; kc++) {
            int xl = (lane ^ kc) << 2;
            float4 fa[4];
#pragma unroll
            for (int mt = 0; mt < 4; mt++)
                fa[mt] = *(const float4*)&As[st][kc][wm * 4 + mt][xl];
            float4 fb0 = *(const float4*)&Bs[st][kc][wn][0][xl];
            float4 fb1 = *(const float4*)&Bs[st][kc][wn][1][xl];
#pragma unroll
            for (int mt = 0; mt < 4; mt++) {
                mma8(acc[mt][0], fa[mt], fb0.x, fb0.y);
                mma8(acc[mt][1], fa[mt], fb0.z, fb0.w);
                mma8(acc[mt][2], fa[mt], fb1.x, fb1.y);
                mma8(acc[mt][3], fa[mt], fb1.z, fb1.w);
            }
        }
        if (kb + 1 < nk) {
            sts((kb + 1) & 1);
            __syncthreads();
        }
    }

    // Epilogue. c0:(g,2q) c1:(g,2q+1) c2:(g+8,2q) c3:(g+8,2q+1)
#pragma unroll
    for (int mt = 0; mt < 4; mt++) {
#pragma unroll
        for (int half = 0; half < 2; half++) {
            int row  = bm + wm * 64 + mt * 16 + gid + half * 8;
            int orow = (EPI == 1) ? win_row_to_token(row) : row;
#pragma unroll
            for (int nt = 0; nt < 4; nt++) {
                int col = bn + wn * 32 + nt * 8 + qid * 2;
                float v0 = acc[mt][nt][half * 2 + 0] + bias[col];
                float v1 = acc[mt][nt][half * 2 + 1] + bias[col + 1];
                if (EPI == 2) {
                    v0 = tf32r(0.5f * v0 * (1.f + erff(v0 * 0.70710678118654752f)));
                    v1 = tf32r(0.5f * v1 * (1.f + erff(v1 * 0.70710678118654752f)));
                }
                if (EPI == 3) {
                    v0 += resid[(size_t)row * CC + col];
                    v1 += resid[(size_t)row * CC + col + 1];
                }
                float2 o = make_float2(v0, v1);
                *(float2*)&Cout[(size_t)orow * Nn + col] = o;
            }
        }
    }
}

// Tensor-core attention: one CTA per (window, head), 4 warps.
// S = (Q*scale) K^T + mask; softmax; O = P V. All mma tf32.
__global__ void __launch_bounds__(128)
attn_kernel(const float* __restrict__ qkv, const float* __restrict__ mask,
            float* __restrict__ out)
{
    int win  = blockIdx.x / NHEAD;
    int head = blockIdx.x % NHEAD;
    __shared__ float qs[64 * 33];   // Q rows (m x k), rows 49..63 zero
    __shared__ float kt[32 * 57];   // K^T: [d][j], cols 49..55 zero
    __shared__ float vs[56 * 36];   // V: [j][d], rows 49..55 zero
    __shared__ float sm[64 * 57];   // S then P (m x k), cols 49..55 stay zero

    const int tid = threadIdx.x;
    const int warp = tid >> 5, lane = tid & 31;
    const int gid = lane >> 2, qid = lane & 3;
    const int m0 = warp * 16;
    const float scale = 0.17677669529663687f;  // 1/sqrt(32)

    for (int t = tid; t < 64 * 33; t += 128) qs[t] = 0.f;
    for (int t = tid; t < 32 * 57; t += 128) kt[t] = 0.f;
    for (int t = tid; t < 56 * 36; t += 128) vs[t] = 0.f;
    __syncthreads();

    const float* base = qkv + (size_t)win * 49 * (3 * CC);
    for (int t = tid; t < 49 * 32; t += 128) {
        int r = t >> 5, c = t & 31;
        qs[r * 33 + c] = tf32r(base[r * (3 * CC) +          head * 32 + c] * scale);
        kt[c * 57 + r] = tf32r(base[r * (3 * CC) + CC     + head * 32 + c]);
        vs[r * 36 + c] = tf32r(base[r * (3 * CC) + 2 * CC + head * 32 + c]);
    }
    __syncthreads();

    // S = Q K^T : warp rows [m0, m0+16), 7 n-tiles (j to 56), k = 32
    {
        float sacc[7][4] = {};
#pragma unroll
        for (int kk = 0; kk < 4; kk++) {
            int k = kk * 8;
            float4 a = make_float4(qs[(m0 + gid) * 33 + k + qid],
                                   qs[(m0 + gid + 8) * 33 + k + qid],
                                   qs[(m0 + gid) * 33 + k + qid + 4],
                                   qs[(m0 + gid + 8) * 33 + k + qid + 4]);
#pragma unroll
            for (int nt = 0; nt < 7; nt++) {
                float b0 = kt[(k + qid) * 57 + nt * 8 + gid];
                float b1 = kt[(k + qid + 4) * 57 + nt * 8 + gid];
                mma8(sacc[nt], a, b0, b1);
            }
        }
#pragma unroll
        for (int nt = 0; nt < 7; nt++) {
            int j = nt * 8 + qid * 2;
            sm[(m0 + gid) * 57 + j]     = sacc[nt][0];
            sm[(m0 + gid) * 57 + j + 1] = sacc[nt][1];
            sm[(m0 + gid + 8) * 57 + j]     = sacc[nt][2];
            sm[(m0 + gid + 8) * 57 + j + 1] = sacc[nt][3];
        }
    }
    __syncthreads();

    // masked softmax over rows 0..48 (cols 0..48); P written tf32-rounded
    const float* mk = mask + (size_t)(win & 63) * 49 * 49;
    for (int r = warp; r < 49; r += 4) {
        float v0 = sm[r * 57 + lane] + mk[r * 49 + lane];
        float v1 = (lane < 17) ? sm[r * 57 + 32 + lane] + mk[r * 49 + 32 + lane] : -1e30f;
        float m = fmaxf(v0, v1);
#pragma unroll
        for (int o = 16; o; o >>= 1) m = fmaxf(m, __shfl_xor_sync(0xffffffffu, m, o));
        float e0 = __expf(v0 - m);
        float e1 = (lane < 17) ? __expf(v1 - m) : 0.f;
        float s = e0 + e1;
#pragma unroll
        for (int o = 16; o; o >>= 1) s += __shfl_xor_sync(0xffffffffu, s, o);
        float inv = 1.f / s;
        sm[r * 57 + lane] = tf32r(e0 * inv);
        if (lane < 17) sm[r * 57 + 32 + lane] = tf32r(e1 * inv);
    }
    __syncthreads();

    // O = P V : k runs to 56 (pad zero), n = 32
    {
        float oacc[4][4] = {};
#pragma unroll
        for (int kk = 0; kk < 7; kk++) {
            int k = kk * 8;
            float4 a = make_float4(sm[(m0 + gid) * 57 + k + qid],
                                   sm[(m0 + gid + 8) * 57 + k + qid],
                                   sm[(m0 + gid) * 57 + k + qid + 4],
                                   sm[(m0 + gid + 8) * 57 + k + qid + 4]);
#pragma unroll
            for (int nt = 0; nt < 4; nt++) {
                float b0 = vs[(k + qid) * 36 + nt * 8 + gid];
                float b1 = vs[(k + qid + 4) * 36 + nt * 8 + gid];
                mma8(oacc[nt], a, b0, b1);
            }
        }
        int i0 = m0 + gid, i1 = m0 + gid + 8;
        float* o0 = out + ((size_t)win * 49 + i0) * CC + head * 32;
        float* o1 = out + ((size_t)win * 49 + i1) * CC + head * 32;
#pragma unroll
        for (int nt = 0; nt < 4; nt++) {
            int d = nt * 8 + qid * 2;
            if (i0 < 49) {
                o0[d]     = tf32r(oacc[nt][0]);
                o0[d + 1] = tf32r(oacc[nt][1]);
            }
            if (i1 < 49) {
                o1[d]     = tf32r(oacc[nt][2]);
                o1[d + 1] = tf32r(oacc[nt][3]);
            }
        }
    }
}

extern "C" void kernel_launch(void* const* d_in, const int* in_sizes, int n_in,
                              void* d_out, int out_size)
{
    const float* x      = (const float*)d_in[0];
    const float* qkv_w  = (const float*)d_in[1];
    const float* qkv_b  = (const float*)d_in[2];
    const float* proj_w = (const float*)d_in[3];
    const float* proj_b = (const float*)d_in[4];
    const float* n1g    = (const float*)d_in[5];
    const float* n1b    = (const float*)d_in[6];
    const float* n2g    = (const float*)d_in[7];
    const float* n2b    = (const float*)d_in[8];
    const float* fc1w   = (const float*)d_in[9];
    const float* fc1b   = (const float*)d_in[10];
    const float* fc2w   = (const float*)d_in[11];
    const float* fc2b   = (const float*)d_in[12];
    const float* amask  = (const float*)d_in[13];
    float* out = (float*)d_out;

    float *xn, *qkv, *att, *xr, *h, *h1, *w;
    cudaGetSymbolAddress((void**)&xn,  g_xn);
    cudaGetSymbolAddress((void**)&qkv, g_qkv);
    cudaGetSymbolAddress((void**)&att, g_att);
    cudaGetSymbolAddress((void**)&xr,  g_xr);
    cudaGetSymbolAddress((void**)&h,   g_h);
    cudaGetSymbolAddress((void**)&h1,  g_h1);
    cudaGetSymbolAddress((void**)&w,   g_w);

    // 0) pre-round weights to tf32
    round_w<<<(110592 + 255) / 256, 256>>>(qkv_w,  w + OFF_QKVW, 110592);
    round_w<<<(36864  + 255) / 256, 256>>>(proj_w, w + OFF_PROJW, 36864);
    round_w<<<(147456 + 255) / 256, 256>>>(fc1w,   w + OFF_FC1W, 147456);
    round_w<<<(147456 + 255) / 256, 256>>>(fc2w,   w + OFF_FC2W, 147456);

    dim3 lnb(32, 8);
    // 1) shift + window partition + LN1 (fused permutation), tf32-rounded out
    ln_kernel<<<TOK / 8, lnb>>>(x, n1g, n1b, xn, 1);
    // 2) QKV GEMM: (100352,192) @ (192,576)
    tgemm<0><<<dim3(9, 784), 128>>>(xn, w + OFF_QKVW, qkv_b, qkv, 576, 192, nullptr);
    // 3) windowed attention per (window, head), tensor cores
    attn_kernel<<<NWIN * NHEAD, 128>>>(qkv, amask, att);
    // 4) proj GEMM + un-window + un-shift write into xr (token order)
    tgemm<1><<<dim3(3, 784), 128>>>(att, w + OFF_PROJW, proj_b, xr, 192, 192, nullptr);
    // 5) LN2, tf32-rounded out
    ln_kernel<<<TOK / 8, lnb>>>(xr, n2g, n2b, h, 0);
    // 6) fc1 + exact GELU, tf32-rounded out
    tgemm<2><<<dim3(12, 784), 128>>>(h, w + OFF_FC1W, fc1b, h1, 768, 192, nullptr);
    // 7) fc2 + bias + residual -> d_out
    tgemm<3><<<dim3(3, 784), 128>>>(h1, w + OFF_FC2W, fc2b, out, 192, 768, xr);
}

// round 6
// speedup vs baseline: 3.1416x; 1.1944x over previous
#include <cuda_runtime.h>
#include <math.h>
#include <stdint.h>

#define TOK   100352          // B*H*W tokens
#define CC    192
#define NHEAD 6
#define HDIM  32
#define NWIN  2048            // B * 64 windows
#define HIDN  768

// Scratch (allocation-free rule: __device__ globals)
__device__ float g_xn [TOK * CC];        // LN1 output (tf32-rounded), window order
__device__ float g_qkv[TOK * 3 * CC];    // qkv, window order (fp32)
__device__ float g_att[TOK * CC];        // attention output (tf32-rounded), window order
__device__ float g_xr [TOK * CC];        // residual branch, token order (fp32)
__device__ float g_h  [TOK * CC];        // LN2 output (tf32-rounded), token order
__device__ float g_h1 [TOK * HIDN];      // fc1+gelu output (tf32-rounded)
__device__ float g_w  [442368];          // tf32-rounded weights (qkv|proj|fc1|fc2)

#define OFF_QKVW  0
#define OFF_PROJW 110592
#define OFF_FC1W  147456
#define OFF_FC2W  294912

__device__ __forceinline__ int win_row_to_token(int row) {
    int win = row / 49, n = row % 49;
    int b   = win >> 6, wij = win & 63;
    int wi  = wij >> 3, wj  = wij & 7;
    int hh  = wi * 7 + n / 7;
    int ww  = wj * 7 + n % 7;
    int h = hh + 3; if (h >= 56) h -= 56;
    int w = ww + 3; if (w >= 56) w -= 56;
    return b * 3136 + h * 56 + w;
}

__device__ __forceinline__ float tf32r(float x) {
    uint32_t u;
    asm("cvt.rna.tf32.f32 %0, %1;" : "=r"(u) : "f"(x));
    return __uint_as_float(u);
}

__device__ __forceinline__ void mma8(float* c, const float4 a, const float bx, const float by) {
    asm volatile(
        "mma.sync.aligned.m16n8k8.row.col.f32.tf32.tf32.f32 "
        "{%0,%1,%2,%3},{%4,%5,%6,%7},{%8,%9},{%0,%1,%2,%3};"
        : "+f"(c[0]), "+f"(c[1]), "+f"(c[2]), "+f"(c[3])
        : "r"(__float_as_uint(a.x)), "r"(__float_as_uint(a.y)),
          "r"(__float_as_uint(a.z)), "r"(__float_as_uint(a.w)),
          "r"(__float_as_uint(bx)), "r"(__float_as_uint(by)));
}

__global__ void round_w(const float* __restrict__ w, float* __restrict__ o, int n) {
    int i = blockIdx.x * 256 + threadIdx.x;
    if (i < n) o[i] = tf32r(w[i]);
}

// LayerNorm over C=192, one warp per row; output tf32-rounded.
__global__ void ln_kernel(const float* __restrict__ x, const float* __restrict__ g,
                          const float* __restrict__ bta, float* __restrict__ out,
                          int permute)
{
    int row  = blockIdx.x * 8 + threadIdx.y;
    int lane = threadIdx.x;
    int src  = permute ? win_row_to_token(row) : row;
    const float* xp = x + (size_t)src * CC;
    float v[6];
    float s = 0.f, s2 = 0.f;
#pragma unroll
    for (int i = 0; i < 6; i++) {
        v[i] = xp[i * 32 + lane];
        s += v[i]; s2 += v[i] * v[i];
    }
#pragma unroll
    for (int o = 16; o; o >>= 1) {
        s  += __shfl_xor_sync(0xffffffffu, s, o);
        s2 += __shfl_xor_sync(0xffffffffu, s2, o);
    }
    float mu  = s * (1.f / 192.f);
    float var = s2 * (1.f / 192.f) - mu * mu;
    float inv = rsqrtf(var + 1e-5f);
    float* op = out + (size_t)row * CC;
#pragma unroll
    for (int i = 0; i < 6; i++) {
        int c = i * 32 + lane;
        op[c] = tf32r((v[i] - mu) * inv * g[c] + bta[c]);
    }
}

// TF32 mma.sync GEMM: CTA 256x64, 4 warps stacked in M, warp tile 64x64.
// A: cp.async into row-major smem (pad 36 floats/row), double buffered.
// B: register-staged fragment layout (round-4 scheme), LDS.128 reads.
// EPI: 0 bias; 1 bias+permuted write; 2 bias+GELU; 3 bias+residual.
template<int EPI>
__global__ void __launch_bounds__(128)
tgemm(const float* __restrict__ A, const float* __restrict__ Bw,
      const float* __restrict__ bias, float* __restrict__ Cout,
      int Nn, int K, const float* __restrict__ resid)
{
    extern __shared__ float dsm[];
    float* Asm = dsm;                        // [2][256*36] = 73728 B
    float* Bsm = dsm + 2 * 256 * 36;         // [2][4 kc][4 sg][128] = 16384 B

    const int tid  = threadIdx.x;
    const int warp = tid >> 5, lane = tid & 31;
    const int gid = lane >> 2, qid = lane & 3;
    const int bm = blockIdx.y * 256, bn = blockIdx.x * 64;
    const int nk = K >> 5;

    float acc[4][8][4] = {};
    float4 breg[4];

    const int br = tid >> 4, bc4 = (tid & 15) * 4;
    const int b_sg = bc4 >> 4, b_np = (bc4 >> 3) & 1, b_g0 = bc4 & 7;

    const uint32_t asm_base = (uint32_t)__cvta_generic_to_shared(Asm);

    auto issueA = [&](int c) {
        int k0 = c << 5, st = c & 1;
        uint32_t dstb = asm_base + (uint32_t)(st * 9216 * 4);
#pragma unroll
        for (int i = 0; i < 16; i++) {
            int slot = tid + i * 128;
            int row = slot >> 3, col4 = (slot & 7) * 4;
            const float* src = &A[(size_t)(bm + row) * K + k0 + col4];
            uint32_t dst = dstb + (uint32_t)((row * 36 + col4) * 4);
            asm volatile("cp.async.cg.shared.global [%0], [%1], 16;"
                         :: "r"(dst), "l"(src));
        }
        asm volatile("cp.async.commit_group;" ::: "memory");
    };
    auto ldgB = [&](int c) {
        int k0 = c << 5;
#pragma unroll
        for (int p = 0; p < 4; p++)
            breg[p] = *(const float4*)&Bw[(size_t)(k0 + br + p * 8) * Nn + bn + bc4];
    };
    auto stsB = [&](int st) {
        float* bb = Bsm + st * 2048;
#pragma unroll
        for (int p = 0; p < 4; p++) {
            int k = br + p * 8;
            int kc = k >> 3, q = k & 3, h = (k >> 2) & 1;
            int e = b_np * 2 + h;
            float* grp = bb + (kc * 4 + b_sg) * 128;
            grp[((((b_g0 + 0) * 4 + q) ^ kc) << 2) + e] = breg[p].x;
            grp[((((b_g0 + 1) * 4 + q) ^ kc) << 2) + e] = breg[p].y;
            grp[((((b_g0 + 2) * 4 + q) ^ kc) << 2) + e] = breg[p].z;
            grp[((((b_g0 + 3) * 4 + q) ^ kc) << 2) + e] = breg[p].w;
        }
    };

    issueA(0);
    ldgB(0);
    asm volatile("cp.async.wait_group 0;" ::: "memory");
    stsB(0);
    __syncthreads();

    for (int c = 0; c < nk; c++) {
        int st = c & 1;
        if (c + 1 < nk) { issueA(c + 1); ldgB(c + 1); }

        const float* ab = Asm + st * 9216;
        const float* bb = Bsm + st * 2048;
#pragma unroll
        for (int kc = 0; kc < 4; kc++) {
            int xl = (lane ^ kc) << 2;
            float4 fb[4];
#pragma unroll
            for (int s = 0; s < 4; s++)
                fb[s] = *(const float4*)&bb[(kc * 4 + s) * 128 + xl];
            float4 fa[4];
#pragma unroll
            for (int mt = 0; mt < 4; mt++) {
                int r = warp * 64 + mt * 16;
                int kk = kc * 8;
                fa[mt].x = ab[(r + gid)     * 36 + kk + qid];
                fa[mt].y = ab[(r + gid + 8) * 36 + kk + qid];
                fa[mt].z = ab[(r + gid)     * 36 + kk + qid + 4];
                fa[mt].w = ab[(r + gid + 8) * 36 + kk + qid + 4];
            }
#pragma unroll
            for (int mt = 0; mt < 4; mt++)
#pragma unroll
                for (int s = 0; s < 4; s++) {
                    mma8(acc[mt][s * 2],     fa[mt], fb[s].x, fb[s].y);
                    mma8(acc[mt][s * 2 + 1], fa[mt], fb[s].z, fb[s].w);
                }
        }

        if (c + 1 < nk) {
            stsB((c + 1) & 1);
            asm volatile("cp.async.wait_group 0;" ::: "memory");
            __syncthreads();
        }
    }

    // Epilogue. acc frag: c0:(g,2q) c1:(g,2q+1) c2:(g+8,2q) c3:(g+8,2q+1)
#pragma unroll
    for (int mt = 0; mt < 4; mt++) {
#pragma unroll
        for (int half = 0; half < 2; half++) {
            int row  = bm + warp * 64 + mt * 16 + gid + half * 8;
            int orow = (EPI == 1) ? win_row_to_token(row) : row;
#pragma unroll
            for (int nt = 0; nt < 8; nt++) {
                int col = bn + nt * 8 + qid * 2;
                float v0 = acc[mt][nt][half * 2 + 0] + bias[col];
                float v1 = acc[mt][nt][half * 2 + 1] + bias[col + 1];
                if (EPI == 2) {
                    v0 = tf32r(0.5f * v0 * (1.f + erff(v0 * 0.70710678118654752f)));
                    v1 = tf32r(0.5f * v1 * (1.f + erff(v1 * 0.70710678118654752f)));
                }
                if (EPI == 3) {
                    v0 += resid[(size_t)row * CC + col];
                    v1 += resid[(size_t)row * CC + col + 1];
                }
                float2 o = make_float2(v0, v1);
                *(float2*)&Cout[(size_t)orow * Nn + col] = o;
            }
        }
    }
}

// Tensor-core attention: one CTA per (window, head), 4 warps. (round-4 proven)
__global__ void __launch_bounds__(128)
attn_kernel(const float* __restrict__ qkv, const float* __restrict__ mask,
            float* __restrict__ out)
{
    int win  = blockIdx.x / NHEAD;
    int head = blockIdx.x % NHEAD;
    __shared__ float qs[64 * 33];
    __shared__ float kt[32 * 57];
    __shared__ float vs[56 * 36];
    __shared__ float sm[64 * 57];

    const int tid = threadIdx.x;
    const int warp = tid >> 5, lane = tid & 31;
    const int gid = lane >> 2, qid = lane & 3;
    const int m0 = warp * 16;
    const float scale = 0.17677669529663687f;

    for (int t = tid; t < 64 * 33; t += 128) qs[t] = 0.f;
    for (int t = tid; t < 32 * 57; t += 128) kt[t] = 0.f;
    for (int t = tid; t < 56 * 36; t += 128) vs[t] = 0.f;
    __syncthreads();

    const float* base = qkv + (size_t)win * 49 * (3 * CC);
    for (int t = tid; t < 49 * 32; t += 128) {
        int r = t >> 5, c = t & 31;
        qs[r * 33 + c] = tf32r(base[r * (3 * CC) +          head * 32 + c] * scale);
        kt[c * 57 + r] = tf32r(base[r * (3 * CC) + CC     + head * 32 + c]);
        vs[r * 36 + c] = tf32r(base[r * (3 * CC) + 2 * CC + head * 32 + c]);
    }
    __syncthreads();

    {
        float sacc[7][4] = {};
#pragma unroll
        for (int kk = 0; kk < 4; kk++) {
            int k = kk * 8;
            float4 a = make_float4(qs[(m0 + gid) * 33 + k + qid],
                                   qs[(m0 + gid + 8) * 33 + k + qid],
                                   qs[(m0 + gid) * 33 + k + qid + 4],
                                   qs[(m0 + gid + 8) * 33 + k + qid + 4]);
#pragma unroll
            for (int nt = 0; nt < 7; nt++) {
                float b0 = kt[(k + qid) * 57 + nt * 8 + gid];
                float b1 = kt[(k + qid + 4) * 57 + nt * 8 + gid];
                mma8(sacc[nt], a, b0, b1);
            }
        }
#pragma unroll
        for (int nt = 0; nt < 7; nt++) {
            int j = nt * 8 + qid * 2;
            sm[(m0 + gid) * 57 + j]     = sacc[nt][0];
            sm[(m0 + gid) * 57 + j + 1] = sacc[nt][1];
            sm[(m0 + gid + 8) * 57 + j]     = sacc[nt][2];
            sm[(m0 + gid + 8) * 57 + j + 1] = sacc[nt][3];
        }
    }
    __syncthreads();

    const float* mk = mask + (size_t)(win & 63) * 49 * 49;
    for (int r = warp; r < 49; r += 4) {
        float v0 = sm[r * 57 + lane] + mk[r * 49 + lane];
        float v1 = (lane < 17) ? sm[r * 57 + 32 + lane] + mk[r * 49 + 32 + lane] : -1e30f;
        float m = fmaxf(v0, v1);
#pragma unroll
        for (int o = 16; o; o >>= 1) m = fmaxf(m, __shfl_xor_sync(0xffffffffu, m, o));
        float e0 = __expf(v0 - m);
        float e1 = (lane < 17) ? __expf(v1 - m) : 0.f;
        float s = e0 + e1;
#pragma unroll
        for (int o = 16; o; o >>= 1) s += __shfl_xor_sync(0xffffffffu, s, o);
        float inv = 1.f / s;
        sm[r * 57 + lane] = tf32r(e0 * inv);
        if (lane < 17) sm[r * 57 + 32 + lane] = tf32r(e1 * inv);
    }
    __syncthreads();

    {
        float oacc[4][4] = {};
#pragma unroll
        for (int kk = 0; kk < 7; kk++) {
            int k = kk * 8;
            float4 a = make_float4(sm[(m0 + gid) * 57 + k + qid],
                                   sm[(m0 + gid + 8) * 57 + k + qid],
                                   sm[(m0 + gid) * 57 + k + qid + 4],
                                   sm[(m0 + gid + 8) * 57 + k + qid + 4]);
#pragma unroll
            for (int nt = 0; nt < 4; nt++) {
                float b0 = vs[(k + qid) * 36 + nt * 8 + gid];
                float b1 = vs[(k + qid + 4) * 36 + nt * 8 + gid];
                mma8(oacc[nt], a, b0, b1);
            }
        }
        int i0 = m0 + gid, i1 = m0 + gid + 8;
        float* o0 = out + ((size_t)win * 49 + i0) * CC + head * 32;
        float* o1 = out + ((size_t)win * 49 + i1) * CC + head * 32;
#pragma unroll
        for (int nt = 0; nt < 4; nt++) {
            int d = nt * 8 + qid * 2;
            if (i0 < 49) {
                o0[d]     = tf32r(oacc[nt][0]);
                o0[d + 1] = tf32r(oacc[nt][1]);
            }
            if (i1 < 49) {
                o1[d]     = tf32r(oacc[nt][2]);
                o1[d + 1] = tf32r(oacc[nt][3]);
            }
        }
    }
}

extern "C" void kernel_launch(void* const* d_in, const int* in_sizes, int n_in,
                              void* d_out, int out_size)
{
    const float* x      = (const float*)d_in[0];
    const float* qkv_w  = (const float*)d_in[1];
    const float* qkv_b  = (const float*)d_in[2];
    const float* proj_w = (const float*)d_in[3];
    const float* proj_b = (const float*)d_in[4];
    const float* n1g    = (const float*)d_in[5];
    const float* n1b    = (const float*)d_in[6];
    const float* n2g    = (const float*)d_in[7];
    const float* n2b    = (const float*)d_in[8];
    const float* fc1w   = (const float*)d_in[9];
    const float* fc1b   = (const float*)d_in[10];
    const float* fc2w   = (const float*)d_in[11];
    const float* fc2b   = (const float*)d_in[12];
    const float* amask  = (const float*)d_in[13];
    float* out = (float*)d_out;

    float *xn, *qkv, *att, *xr, *h, *h1, *w;
    cudaGetSymbolAddress((void**)&xn,  g_xn);
    cudaGetSymbolAddress((void**)&qkv, g_qkv);
    cudaGetSymbolAddress((void**)&att, g_att);
    cudaGetSymbolAddress((void**)&xr,  g_xr);
    cudaGetSymbolAddress((void**)&h,   g_h);
    cudaGetSymbolAddress((void**)&h1,  g_h1);
    cudaGetSymbolAddress((void**)&w,   g_w);

    const int SMEM_GEMM = 90112;   // 73728 (A) + 16384 (B)
    cudaFuncSetAttribute(tgemm<0>, cudaFuncAttributeMaxDynamicSharedMemorySize, SMEM_GEMM);
    cudaFuncSetAttribute(tgemm<1>, cudaFuncAttributeMaxDynamicSharedMemorySize, SMEM_GEMM);
    cudaFuncSetAttribute(tgemm<2>, cudaFuncAttributeMaxDynamicSharedMemorySize, SMEM_GEMM);
    cudaFuncSetAttribute(tgemm<3>, cudaFuncAttributeMaxDynamicSharedMemorySize, SMEM_GEMM);

    // 0) pre-round weights to tf32
    round_w<<<(110592 + 255) / 256, 256>>>(qkv_w,  w + OFF_QKVW, 110592);
    round_w<<<(36864  + 255) / 256, 256>>>(proj_w, w + OFF_PROJW, 36864);
    round_w<<<(147456 + 255) / 256, 256>>>(fc1w,   w + OFF_FC1W, 147456);
    round_w<<<(147456 + 255) / 256, 256>>>(fc2w,   w + OFF_FC2W, 147456);

    dim3 lnb(32, 8);
    // 1) shift + window partition + LN1
    ln_kernel<<<TOK / 8, lnb>>>(x, n1g, n1b, xn, 1);
    // 2) QKV GEMM (100352,192)@(192,576)
    tgemm<0><<<dim3(9, 392), 128, SMEM_GEMM>>>(xn, w + OFF_QKVW, qkv_b, qkv, 576, 192, nullptr);
    // 3) windowed attention
    attn_kernel<<<NWIN * NHEAD, 128>>>(qkv, amask, att);
    // 4) proj GEMM + un-window/un-shift
    tgemm<1><<<dim3(3, 392), 128, SMEM_GEMM>>>(att, w + OFF_PROJW, proj_b, xr, 192, 192, nullptr);
    // 5) LN2
    ln_kernel<<<TOK / 8, lnb>>>(xr, n2g, n2b, h, 0);
    // 6) fc1 + exact GELU
    tgemm<2><<<dim3(12, 392), 128, SMEM_GEMM>>>(h, w + OFF_FC1W, fc1b, h1, 768, 192, nullptr);
    // 7) fc2 + bias + residual -> out
    tgemm<3><<<dim3(3, 392), 128, SMEM_GEMM>>>(h1, w + OFF_FC2W, fc2b, out, 192, 768, xr);
}

// round 7
// speedup vs baseline: 3.6338x; 1.1567x over previous
#include <cuda_runtime.h>
#include <math.h>
#include <stdint.h>

#define TOK   100352          // B*H*W tokens
#define CC    192
#define NHEAD 6
#define HDIM  32
#define NWIN  2048            // B * 64 windows
#define HIDN  768

// Scratch (allocation-free rule: __device__ globals).
// xn/att/h/h1 are stored as A-fragment images (consumed only as GEMM A).
__device__ float g_xn [TOK * CC];
__device__ float g_qkv[TOK * 3 * CC];    // linear (read by attention)
__device__ float g_att[TOK * CC];
__device__ float g_xr [TOK * CC];        // linear (residual + LN2 input)
__device__ float g_h  [TOK * CC];
__device__ float g_h1 [TOK * HIDN];
__device__ float g_w  [442368];          // B fragment images (qkv|proj|fc1|fc2)

#define OFF_QKVW  0
#define OFF_PROJW 110592
#define OFF_FC1W  147456
#define OFF_FC2W  294912

__device__ __forceinline__ int win_row_to_token(int row) {
    int win = row / 49, n = row % 49;
    int b   = win >> 6, wij = win & 63;
    int wi  = wij >> 3, wj  = wij & 7;
    int hh  = wi * 7 + n / 7;
    int ww  = wj * 7 + n % 7;
    int h = hh + 3; if (h >= 56) h -= 56;
    int w = ww + 3; if (w >= 56) w -= 56;
    return b * 3136 + h * 56 + w;
}

__device__ __forceinline__ float tf32r(float x) {
    uint32_t u;
    asm("cvt.rna.tf32.f32 %0, %1;" : "=r"(u) : "f"(x));
    return __uint_as_float(u);
}

// A-fragment image index for element (row, col) of an [*, K] activation.
// Image: [mblock256][chunk32][ (m16*4+kc)*128 + lane*4 + j ]  (8192 f/chunk)
__device__ __forceinline__ size_t aimg_idx(int row, int col, int K) {
    int nk  = K >> 5;
    int mb  = row >> 8, m = row & 255;
    int ch  = col >> 5, kin = col & 31;
    int m16 = m >> 4, rr = m & 15;
    int kc  = kin >> 3;
    int lane = (rr & 7) * 4 + (kin & 3);
    int j    = (rr >> 3) + ((kin >> 2) & 1) * 2;
    return ((size_t)mb * nk + ch) * 8192 + (size_t)((m16 * 4 + kc) * 128 + lane * 4 + j);
}

__device__ __forceinline__ void mma8(float* c, const float4 a, const float bx, const float by) {
    asm volatile(
        "mma.sync.aligned.m16n8k8.row.col.f32.tf32.tf32.f32 "
        "{%0,%1,%2,%3},{%4,%5,%6,%7},{%8,%9},{%0,%1,%2,%3};"
        : "+f"(c[0]), "+f"(c[1]), "+f"(c[2]), "+f"(c[3])
        : "r"(__float_as_uint(a.x)), "r"(__float_as_uint(a.y)),
          "r"(__float_as_uint(a.z)), "r"(__float_as_uint(a.w)),
          "r"(__float_as_uint(bx)), "r"(__float_as_uint(by)));
}

// B-fragment image prep: weight W[K,N] -> per (x-block, chunk) 8KB images
// matching the round-6 stsB layout, tf32-rounded.
__global__ void prep_b(const float* __restrict__ W, float* __restrict__ dst,
                       int K, int N) {
    int idx = blockIdx.x * 256 + threadIdx.x;
    if (idx >= K * N) return;
    int k = idx / N, n = idx % N;
    float v = tf32r(W[idx]);
    int nk = K >> 5;
    int bx = n >> 6, n64 = n & 63;
    int ch = k >> 5, kin = k & 31;
    int kc = kin >> 3, q = kin & 3, h = (kin >> 2) & 1;
    int sg = n64 >> 4, np = (n64 >> 3) & 1, g = n64 & 7;
    size_t pos = ((size_t)bx * nk + ch) * 2048
               + (size_t)((kc * 4 + sg) * 128 + ((((g * 4 + q)) ^ kc) << 2) + np * 2 + h);
    dst[pos] = v;
}

// LayerNorm over C=192, one warp per row; writes A-fragment image (tf32).
__global__ void ln_kernel(const float* __restrict__ x, const float* __restrict__ g,
                          const float* __restrict__ bta, float* __restrict__ out,
                          int permute)
{
    int row  = blockIdx.x * 8 + threadIdx.y;
    int lane = threadIdx.x;
    int src  = permute ? win_row_to_token(row) : row;
    const float* xp = x + (size_t)src * CC;
    float v[6];
    float s = 0.f, s2 = 0.f;
#pragma unroll
    for (int i = 0; i < 6; i++) {
        v[i] = xp[i * 32 + lane];
        s += v[i]; s2 += v[i] * v[i];
    }
#pragma unroll
    for (int o = 16; o; o >>= 1) {
        s  += __shfl_xor_sync(0xffffffffu, s, o);
        s2 += __shfl_xor_sync(0xffffffffu, s2, o);
    }
    float mu  = s * (1.f / 192.f);
    float var = s2 * (1.f / 192.f) - mu * mu;
    float inv = rsqrtf(var + 1e-5f);
#pragma unroll
    for (int i = 0; i < 6; i++) {
        int c = i * 32 + lane;
        out[aimg_idx(row, c, 192)] = tf32r((v[i] - mu) * inv * g[c] + bta[c]);
    }
}

// TF32 mma.sync GEMM: CTA 256x64, 4 warps stacked in M, warp tile 64x64.
// A and B both pre-formatted fragment images, staged by cp.async,
// double buffered with wait_group 1 overlap. All fragment reads LDS.128.
// EPI: 0 bias; 1 bias+permuted write; 2 bias+GELU -> A-image (K=768); 3 bias+residual.
template<int EPI>
__global__ void __launch_bounds__(128)
tgemm(const float* __restrict__ Aimg, const float* __restrict__ Bimg,
      const float* __restrict__ bias, float* __restrict__ Cout,
      int Nn, int K, const float* __restrict__ resid)
{
    extern __shared__ float dsm[];
    float* Asm = dsm;                // [2][8192] floats = 64KB
    float* Bsm = dsm + 2 * 8192;     // [2][2048] floats = 16KB

    const int tid  = threadIdx.x;
    const int warp = tid >> 5, lane = tid & 31;
    const int gid = lane >> 2, qid = lane & 3;
    const int bm = blockIdx.y * 256, bn = blockIdx.x * 64;
    const int nk = K >> 5;

    float acc[4][8][4] = {};

    const uint32_t asmb = (uint32_t)__cvta_generic_to_shared(Asm);
    const uint32_t bsmb = asmb + 65536;
    const float* Ab = Aimg + (size_t)blockIdx.y * nk * 8192;
    const float* Bb = Bimg + (size_t)blockIdx.x * nk * 2048;

    auto issue = [&](int c) {
        int st = c & 1;
        const float4* as = (const float4*)(Ab + (size_t)c * 8192) + tid;
        uint32_t ad = asmb + (uint32_t)(st * 32768 + tid * 16);
#pragma unroll
        for (int p = 0; p < 16; p++)
            asm volatile("cp.async.cg.shared.global [%0], [%1], 16;"
                         :: "r"(ad + p * 2048), "l"(as + p * 128));
        const float4* bs = (const float4*)(Bb + (size_t)c * 2048) + tid;
        uint32_t bd = bsmb + (uint32_t)(st * 8192 + tid * 16);
#pragma unroll
        for (int p = 0; p < 4; p++)
            asm volatile("cp.async.cg.shared.global [%0], [%1], 16;"
                         :: "r"(bd + p * 2048), "l"(bs + p * 128));
        asm volatile("cp.async.commit_group;" ::: "memory");
    };

    issue(0);
    for (int c = 0; c < nk; c++) {
        if (c + 1 < nk) {
            issue(c + 1);
            asm volatile("cp.async.wait_group 1;" ::: "memory");
        } else {
            asm volatile("cp.async.wait_group 0;" ::: "memory");
        }
        __syncthreads();

        const float* ab = Asm + (c & 1) * 8192;
        const float* bb = Bsm + (c & 1) * 2048;
#pragma unroll
        for (int kc = 0; kc < 4; kc++) {
            int xl = (lane ^ kc) << 2;
            float4 fa[4], fb[4];
#pragma unroll
            for (int mt = 0; mt < 4; mt++)
                fa[mt] = *(const float4*)&ab[((warp * 4 + mt) * 4 + kc) * 128 + lane * 4];
#pragma unroll
            for (int s = 0; s < 4; s++)
                fb[s] = *(const float4*)&bb[(kc * 4 + s) * 128 + xl];
#pragma unroll
            for (int mt = 0; mt < 4; mt++)
#pragma unroll
                for (int s = 0; s < 4; s++) {
                    mma8(acc[mt][s * 2],     fa[mt], fb[s].x, fb[s].y);
                    mma8(acc[mt][s * 2 + 1], fa[mt], fb[s].z, fb[s].w);
                }
        }
        __syncthreads();
    }

    // Epilogue. acc frag: c0:(g,2q) c1:(g,2q+1) c2:(g+8,2q) c3:(g+8,2q+1)
#pragma unroll
    for (int mt = 0; mt < 4; mt++) {
#pragma unroll
        for (int half = 0; half < 2; half++) {
            int row  = bm + warp * 64 + mt * 16 + gid + half * 8;
            int orow = (EPI == 1) ? win_row_to_token(row) : row;
#pragma unroll
            for (int nt = 0; nt < 8; nt++) {
                int col = bn + nt * 8 + qid * 2;
                float v0 = acc[mt][nt][half * 2 + 0] + bias[col];
                float v1 = acc[mt][nt][half * 2 + 1] + bias[col + 1];
                if (EPI == 2) {
                    v0 = tf32r(0.5f * v0 * (1.f + erff(v0 * 0.70710678118654752f)));
                    v1 = tf32r(0.5f * v1 * (1.f + erff(v1 * 0.70710678118654752f)));
                    Cout[aimg_idx(row, col,     768)] = v0;
                    Cout[aimg_idx(row, col + 1, 768)] = v1;
                } else {
                    if (EPI == 3) {
                        v0 += resid[(size_t)row * CC + col];
                        v1 += resid[(size_t)row * CC + col + 1];
                    }
                    float2 o = make_float2(v0, v1);
                    *(float2*)&Cout[(size_t)orow * Nn + col] = o;
                }
            }
        }
    }
}

// Tensor-core attention: one CTA per (window, head), 4 warps.
// Output written as A-fragment image (consumed by proj GEMM).
__global__ void __launch_bounds__(128)
attn_kernel(const float* __restrict__ qkv, const float* __restrict__ mask,
            float* __restrict__ out)
{
    int win  = blockIdx.x / NHEAD;
    int head = blockIdx.x % NHEAD;
    __shared__ float qs[64 * 33];
    __shared__ float kt[32 * 57];
    __shared__ float vs[56 * 36];
    __shared__ float sm[64 * 57];

    const int tid = threadIdx.x;
    const int warp = tid >> 5, lane = tid & 31;
    const int gid = lane >> 2, qid = lane & 3;
    const int m0 = warp * 16;
    const float scale = 0.17677669529663687f;

    for (int t = tid; t < 64 * 33; t += 128) qs[t] = 0.f;
    for (int t = tid; t < 32 * 57; t += 128) kt[t] = 0.f;
    for (int t = tid; t < 56 * 36; t += 128) vs[t] = 0.f;
    __syncthreads();

    const float* base = qkv + (size_t)win * 49 * (3 * CC);
    for (int t = tid; t < 49 * 32; t += 128) {
        int r = t >> 5, c = t & 31;
        qs[r * 33 + c] = tf32r(base[r * (3 * CC) +          head * 32 + c] * scale);
        kt[c * 57 + r] = tf32r(base[r * (3 * CC) + CC     + head * 32 + c]);
        vs[r * 36 + c] = tf32r(base[r * (3 * CC) + 2 * CC + head * 32 + c]);
    }
    __syncthreads();

    {
        float sacc[7][4] = {};
#pragma unroll
        for (int kk = 0; kk < 4; kk++) {
            int k = kk * 8;
            float4 a = make_float4(qs[(m0 + gid) * 33 + k + qid],
                                   qs[(m0 + gid + 8) * 33 + k + qid],
                                   qs[(m0 + gid) * 33 + k + qid + 4],
                                   qs[(m0 + gid + 8) * 33 + k + qid + 4]);
#pragma unroll
            for (int nt = 0; nt < 7; nt++) {
                float b0 = kt[(k + qid) * 57 + nt * 8 + gid];
                float b1 = kt[(k + qid + 4) * 57 + nt * 8 + gid];
                mma8(sacc[nt], a, b0, b1);
            }
        }
#pragma unroll
        for (int nt = 0; nt < 7; nt++) {
            int j = nt * 8 + qid * 2;
            sm[(m0 + gid) * 57 + j]     = sacc[nt][0];
            sm[(m0 + gid) * 57 + j + 1] = sacc[nt][1];
            sm[(m0 + gid + 8) * 57 + j]     = sacc[nt][2];
            sm[(m0 + gid + 8) * 57 + j + 1] = sacc[nt][3];
        }
    }
    __syncthreads();

    const float* mk = mask + (size_t)(win & 63) * 49 * 49;
    for (int r = warp; r < 49; r += 4) {
        float v0 = sm[r * 57 + lane] + mk[r * 49 + lane];
        float v1 = (lane < 17) ? sm[r * 57 + 32 + lane] + mk[r * 49 + 32 + lane] : -1e30f;
        float m = fmaxf(v0, v1);
#pragma unroll
        for (int o = 16; o; o >>= 1) m = fmaxf(m, __shfl_xor_sync(0xffffffffu, m, o));
        float e0 = __expf(v0 - m);
        float e1 = (lane < 17) ? __expf(v1 - m) : 0.f;
        float s = e0 + e1;
#pragma unroll
        for (int o = 16; o; o >>= 1) s += __shfl_xor_sync(0xffffffffu, s, o);
        float inv = 1.f / s;
        sm[r * 57 + lane] = tf32r(e0 * inv);
        if (lane < 17) sm[r * 57 + 32 + lane] = tf32r(e1 * inv);
    }
    __syncthreads();

    {
        float oacc[4][4] = {};
#pragma unroll
        for (int kk = 0; kk < 7; kk++) {
            int k = kk * 8;
            float4 a = make_float4(sm[(m0 + gid) * 57 + k + qid],
                                   sm[(m0 + gid + 8) * 57 + k + qid],
                                   sm[(m0 + gid) * 57 + k + qid + 4],
                                   sm[(m0 + gid + 8) * 57 + k + qid + 4]);
#pragma unroll
            for (int nt = 0; nt < 4; nt++) {
                float b0 = vs[(k + qid) * 36 + nt * 8 + gid];
                float b1 = vs[(k + qid + 4) * 36 + nt * 8 + gid];
                mma8(oacc[nt], a, b0, b1);
            }
        }
        int i0 = m0 + gid, i1 = m0 + gid + 8;
#pragma unroll
        for (int nt = 0; nt < 4; nt++) {
            int d = head * 32 + nt * 8 + qid * 2;
            if (i0 < 49) {
                int r0 = win * 49 + i0;
                out[aimg_idx(r0, d,     192)] = tf32r(oacc[nt][0]);
                out[aimg_idx(r0, d + 1, 192)] = tf32r(oacc[nt][1]);
            }
            if (i1 < 49) {
                int r1 = win * 49 + i1;
                out[aimg_idx(r1, d,     192)] = tf32r(oacc[nt][2]);
                out[aimg_idx(r1, d + 1, 192)] = tf32r(oacc[nt][3]);
            }
        }
    }
}

extern "C" void kernel_launch(void* const* d_in, const int* in_sizes, int n_in,
                              void* d_out, int out_size)
{
    const float* x      = (const float*)d_in[0];
    const float* qkv_w  = (const float*)d_in[1];
    const float* qkv_b  = (const float*)d_in[2];
    const float* proj_w = (const float*)d_in[3];
    const float* proj_b = (const float*)d_in[4];
    const float* n1g    = (const float*)d_in[5];
    const float* n1b    = (const float*)d_in[6];
    const float* n2g    = (const float*)d_in[7];
    const float* n2b    = (const float*)d_in[8];
    const float* fc1w   = (const float*)d_in[9];
    const float* fc1b   = (const float*)d_in[10];
    const float* fc2w   = (const float*)d_in[11];
    const float* fc2b   = (const float*)d_in[12];
    const float* amask  = (const float*)d_in[13];
    float* out = (float*)d_out;

    float *xn, *qkv, *att, *xr, *h, *h1, *w;
    cudaGetSymbolAddress((void**)&xn,  g_xn);
    cudaGetSymbolAddress((void**)&qkv, g_qkv);
    cudaGetSymbolAddress((void**)&att, g_att);
    cudaGetSymbolAddress((void**)&xr,  g_xr);
    cudaGetSymbolAddress((void**)&h,   g_h);
    cudaGetSymbolAddress((void**)&h1,  g_h1);
    cudaGetSymbolAddress((void**)&w,   g_w);

    const int SMEM_GEMM = 81920;   // 64KB A + 16KB B
    cudaFuncSetAttribute(tgemm<0>, cudaFuncAttributeMaxDynamicSharedMemorySize, SMEM_GEMM);
    cudaFuncSetAttribute(tgemm<1>, cudaFuncAttributeMaxDynamicSharedMemorySize, SMEM_GEMM);
    cudaFuncSetAttribute(tgemm<2>, cudaFuncAttributeMaxDynamicSharedMemorySize, SMEM_GEMM);
    cudaFuncSetAttribute(tgemm<3>, cudaFuncAttributeMaxDynamicSharedMemorySize, SMEM_GEMM);

    // 0) build B fragment images (tf32)
    prep_b<<<(110592 + 255) / 256, 256>>>(qkv_w,  w + OFF_QKVW, 192, 576);
    prep_b<<<(36864  + 255) / 256, 256>>>(proj_w, w + OFF_PROJW, 192, 192);
    prep_b<<<(147456 + 255) / 256, 256>>>(fc1w,   w + OFF_FC1W, 192, 768);
    prep_b<<<(147456 + 255) / 256, 256>>>(fc2w,   w + OFF_FC2W, 768, 192);

    dim3 lnb(32, 8);
    // 1) shift + window partition + LN1 -> A-image
    ln_kernel<<<TOK / 8, lnb>>>(x, n1g, n1b, xn, 1);
    // 2) QKV GEMM (100352,192)@(192,576) -> linear qkv
    tgemm<0><<<dim3(9, 392), 128, SMEM_GEMM>>>(xn, w + OFF_QKVW, qkv_b, qkv, 576, 192, nullptr);
    // 3) windowed attention -> A-image
    attn_kernel<<<NWIN * NHEAD, 128>>>(qkv, amask, att);
    // 4) proj GEMM + un-window/un-shift -> linear xr
    tgemm<1><<<dim3(3, 392), 128, SMEM_GEMM>>>(att, w + OFF_PROJW, proj_b, xr, 192, 192, nullptr);
    // 5) LN2 -> A-image
    ln_kernel<<<TOK / 8, lnb>>>(xr, n2g, n2b, h, 0);
    // 6) fc1 + exact GELU -> A-image (K=768)
    tgemm<2><<<dim3(12, 392), 128, SMEM_GEMM>>>(h, w + OFF_FC1W, fc1b, h1, 768, 192, nullptr);
    // 7) fc2 + bias + residual -> out (linear)
    tgemm<3><<<dim3(3, 392), 128, SMEM_GEMM>>>(h1, w + OFF_FC2W, fc2b, out, 192, 768, xr);
}

// round 8
// speedup vs baseline: 5.2217x; 1.4370x over previous
#include <cuda_runtime.h>
#include <cuda_fp16.h>
#include <math.h>
#include <stdint.h>

#define TOK   100352          // B*H*W tokens
#define CC    192
#define NHEAD 6
#define HDIM  32
#define NWIN  2048            // B * 64 windows
#define HIDN  768

// Scratch (allocation-free rule: __device__ globals).
__device__ __half g_xn [TOK * CC];        // LN1 out, A-frag image
__device__ __half g_qkv[TOK * 3 * CC];    // qkv, linear half
__device__ __half g_att[TOK * CC];        // attn out, A-frag image
__device__ float  g_xr [TOK * CC];        // residual branch, fp32 linear
__device__ __half g_h  [TOK * CC];        // LN2 out, A-frag image
__device__ __half g_h1 [TOK * HIDN];      // fc1+gelu out, A-frag image
__device__ __half g_w  [442368];          // B-frag images (qkv|proj|fc1|fc2)

#define OFF_QKVW  0
#define OFF_PROJW 110592
#define OFF_FC1W  147456
#define OFF_FC2W  294912

__device__ __forceinline__ int win_row_to_token(int row) {
    int win = row / 49, n = row % 49;
    int b   = win >> 6, wij = win & 63;
    int wi  = wij >> 3, wj  = wij & 7;
    int hh  = wi * 7 + n / 7;
    int ww  = wj * 7 + n % 7;
    int h = hh + 3; if (h >= 56) h -= 56;
    int w = ww + 3; if (w >= 56) w -= 56;
    return b * 3136 + h * 56 + w;
}

__device__ __forceinline__ float tf32r(float x) {
    uint32_t u;
    asm("cvt.rna.tf32.f32 %0, %1;" : "=r"(u) : "f"(x));
    return __uint_as_float(u);
}

// A-fragment image (half) index for (row, col) of an [*, K] activation.
// m16n8k16 frag: per (m16-tile, kstep16) 512B block; lane*16B holds a0..a3.
__device__ __forceinline__ size_t aimg_idx(int row, int col, int K) {
    int nk  = K >> 5;
    int mb  = row >> 8, m = row & 255;
    int ch  = col >> 5, kin = col & 31;
    int m16 = m >> 4, rr = m & 15;
    int gid = rr & 7, hr = rr >> 3;
    int ks  = kin >> 4, kk = kin & 15;
    int hi  = kk >> 3, q = (kk & 7) >> 1, e = kk & 1;
    int lane = gid * 4 + q;
    int reg  = hi * 2 + hr;
    return ((size_t)mb * nk + ch) * 8192
         + (size_t)((m16 * 2 + ks) * 256 + lane * 8 + reg * 2 + e);
}

// B-fragment image (half) index for weight element (k, n), K the k-dim.
// Per (kstep, n16-pair) 512B block; lane*16B holds nt0{b0,b1} nt1{b0,b1}.
__device__ __forceinline__ size_t bimg_idx(int k, int n, int K) {
    int nk = K >> 5;
    int bx = n >> 6, n64 = n & 63;
    int ch = k >> 5, kin = k & 31;
    int ks = kin >> 4, kk = kin & 15;
    int hi = kk >> 3, q = (kk & 7) >> 1, e = kk & 1;
    int sg = n64 >> 4, ntp = (n64 >> 3) & 1, g = n64 & 7;
    int lane = g * 4 + q;
    return ((size_t)bx * nk + ch) * 2048
         + (size_t)((ks * 4 + sg) * 256 + lane * 8 + ntp * 4 + hi * 2 + e);
}

__device__ __forceinline__ void mma16(float* c, uint4 a, uint32_t b0, uint32_t b1) {
    asm volatile(
        "mma.sync.aligned.m16n8k16.row.col.f32.f16.f16.f32 "
        "{%0,%1,%2,%3},{%4,%5,%6,%7},{%8,%9},{%0,%1,%2,%3};"
        : "+f"(c[0]), "+f"(c[1]), "+f"(c[2]), "+f"(c[3])
        : "r"(a.x), "r"(a.y), "r"(a.z), "r"(a.w), "r"(b0), "r"(b1));
}

__device__ __forceinline__ void mma8(float* c, const float4 a, const float bx, const float by) {
    asm volatile(
        "mma.sync.aligned.m16n8k8.row.col.f32.tf32.tf32.f32 "
        "{%0,%1,%2,%3},{%4,%5,%6,%7},{%8,%9},{%0,%1,%2,%3};"
        : "+f"(c[0]), "+f"(c[1]), "+f"(c[2]), "+f"(c[3])
        : "r"(__float_as_uint(a.x)), "r"(__float_as_uint(a.y)),
          "r"(__float_as_uint(a.z)), "r"(__float_as_uint(a.w)),
          "r"(__float_as_uint(bx)), "r"(__float_as_uint(by)));
}

// B-fragment image prep (fp16).
__global__ void prep_b(const float* __restrict__ W, __half* __restrict__ dst,
                       int K, int N) {
    int idx = blockIdx.x * 256 + threadIdx.x;
    if (idx >= K * N) return;
    int k = idx / N, n = idx % N;
    dst[bimg_idx(k, n, K)] = __float2half_rn(W[idx]);
}

// LayerNorm over C=192, one warp per row; writes half A-frag image.
__global__ void ln_kernel(const float* __restrict__ x, const float* __restrict__ g,
                          const float* __restrict__ bta, __half* __restrict__ out,
                          int permute)
{
    int row  = blockIdx.x * 8 + threadIdx.y;
    int lane = threadIdx.x;
    int src  = permute ? win_row_to_token(row) : row;
    const float* xp = x + (size_t)src * CC;
    float2 v[3];
    float s = 0.f, s2 = 0.f;
#pragma unroll
    for (int i = 0; i < 3; i++) {
        v[i] = *(const float2*)&xp[i * 64 + lane * 2];
        s += v[i].x + v[i].y;
        s2 += v[i].x * v[i].x + v[i].y * v[i].y;
    }
#pragma unroll
    for (int o = 16; o; o >>= 1) {
        s  += __shfl_xor_sync(0xffffffffu, s, o);
        s2 += __shfl_xor_sync(0xffffffffu, s2, o);
    }
    float mu  = s * (1.f / 192.f);
    float var = s2 * (1.f / 192.f) - mu * mu;
    float inv = rsqrtf(var + 1e-5f);
#pragma unroll
    for (int i = 0; i < 3; i++) {
        int c = i * 64 + lane * 2;
        float2 gg = *(const float2*)&g[c];
        float2 bb = *(const float2*)&bta[c];
        float o0 = (v[i].x - mu) * inv * gg.x + bb.x;
        float o1 = (v[i].y - mu) * inv * gg.y + bb.y;
        *(__half2*)&out[aimg_idx(row, c, 192)] = __floats2half2_rn(o0, o1);
    }
}

// FP16 mma.sync GEMM: CTA 256x64, 4 warps stacked in M, warp tile 64x64.
// A/B pre-formatted fp16 fragment images, cp.async double buffered.
// EPI: 0 bias -> half linear; 1 bias+permuted write -> fp32 linear;
//      2 bias+GELU -> half A-image (K'=768); 3 bias+residual -> fp32 linear.
template<int EPI>
__global__ void __launch_bounds__(128)
tgemm(const __half* __restrict__ Aimg, const __half* __restrict__ Bimg,
      const float* __restrict__ bias, void* __restrict__ CoutV,
      int Nn, int K, const float* __restrict__ resid)
{
    extern __shared__ __half dsh[];
    __half* Asm = dsh;                // [2][8192] halves = 32KB
    __half* Bsm = dsh + 2 * 8192;     // [2][2048] halves = 8KB

    const int tid  = threadIdx.x;
    const int warp = tid >> 5, lane = tid & 31;
    const int gid = lane >> 2, qid = lane & 3;
    const int bm = blockIdx.y * 256, bn = blockIdx.x * 64;
    const int nk = K >> 5;

    float acc[4][8][4] = {};

    const uint32_t asmb = (uint32_t)__cvta_generic_to_shared(Asm);
    const uint32_t bsmb = asmb + 32768;
    const __half* Ab = Aimg + (size_t)blockIdx.y * nk * 8192;
    const __half* Bb = Bimg + (size_t)blockIdx.x * nk * 2048;

    auto issue = [&](int c) {
        int st = c & 1;
        const uint4* as = (const uint4*)(Ab + (size_t)c * 8192) + tid;
        uint32_t ad = asmb + (uint32_t)(st * 16384 + tid * 16);
#pragma unroll
        for (int p = 0; p < 8; p++)
            asm volatile("cp.async.cg.shared.global [%0], [%1], 16;"
                         :: "r"(ad + p * 2048), "l"(as + p * 128));
        const uint4* bs = (const uint4*)(Bb + (size_t)c * 2048) + tid;
        uint32_t bd = bsmb + (uint32_t)(st * 4096 + tid * 16);
#pragma unroll
        for (int p = 0; p < 2; p++)
            asm volatile("cp.async.cg.shared.global [%0], [%1], 16;"
                         :: "r"(bd + p * 2048), "l"(bs + p * 128));
        asm volatile("cp.async.commit_group;" ::: "memory");
    };

    issue(0);
    for (int c = 0; c < nk; c++) {
        if (c + 1 < nk) {
            issue(c + 1);
            asm volatile("cp.async.wait_group 1;" ::: "memory");
        } else {
            asm volatile("cp.async.wait_group 0;" ::: "memory");
        }
        __syncthreads();

        const __half* ab = Asm + (c & 1) * 8192;
        const __half* bb = Bsm + (c & 1) * 2048;
#pragma unroll
        for (int ks = 0; ks < 2; ks++) {
            uint4 fa[4], fb[4];
#pragma unroll
            for (int mt = 0; mt < 4; mt++)
                fa[mt] = *(const uint4*)&ab[((warp * 4 + mt) * 2 + ks) * 256 + lane * 8];
#pragma unroll
            for (int s = 0; s < 4; s++)
                fb[s] = *(const uint4*)&bb[(ks * 4 + s) * 256 + lane * 8];
#pragma unroll
            for (int mt = 0; mt < 4; mt++)
#pragma unroll
                for (int s = 0; s < 4; s++) {
                    mma16(acc[mt][s * 2],     fa[mt], fb[s].x, fb[s].y);
                    mma16(acc[mt][s * 2 + 1], fa[mt], fb[s].z, fb[s].w);
                }
        }
        __syncthreads();
    }

    // Epilogue. acc frag: c0:(g,2q) c1:(g,2q+1) c2:(g+8,2q) c3:(g+8,2q+1)
#pragma unroll
    for (int mt = 0; mt < 4; mt++) {
#pragma unroll
        for (int hf = 0; hf < 2; hf++) {
            int row  = bm + warp * 64 + mt * 16 + gid + hf * 8;
            int orow = (EPI == 1) ? win_row_to_token(row) : row;
#pragma unroll
            for (int nt = 0; nt < 8; nt++) {
                int col = bn + nt * 8 + qid * 2;
                float v0 = acc[mt][nt][hf * 2 + 0] + bias[col];
                float v1 = acc[mt][nt][hf * 2 + 1] + bias[col + 1];
                if (EPI == 0) {
                    __half* O = (__half*)CoutV;
                    *(__half2*)&O[(size_t)row * Nn + col] = __floats2half2_rn(v0, v1);
                } else if (EPI == 1) {
                    float* O = (float*)CoutV;
                    *(float2*)&O[(size_t)orow * Nn + col] = make_float2(v0, v1);
                } else if (EPI == 2) {
                    v0 = 0.5f * v0 * (1.f + erff(v0 * 0.70710678118654752f));
                    v1 = 0.5f * v1 * (1.f + erff(v1 * 0.70710678118654752f));
                    __half* O = (__half*)CoutV;
                    *(__half2*)&O[aimg_idx(row, col, 768)] = __floats2half2_rn(v0, v1);
                } else {
                    float* O = (float*)CoutV;
                    float r0 = resid[(size_t)row * CC + col];
                    float r1 = resid[(size_t)row * CC + col + 1];
                    *(float2*)&O[(size_t)row * Nn + col] = make_float2(v0 + r0, v1 + r1);
                }
            }
        }
    }
}

// Tensor-core attention: one CTA per (window, head), 4 warps, tf32 mma.
// Reads half qkv; writes half A-frag image.
__global__ void __launch_bounds__(128)
attn_kernel(const __half* __restrict__ qkv, const float* __restrict__ mask,
            __half* __restrict__ out)
{
    int win  = blockIdx.x / NHEAD;
    int head = blockIdx.x % NHEAD;
    __shared__ float qs[64 * 33];
    __shared__ float kt[32 * 57];
    __shared__ float vs[56 * 36];
    __shared__ float sm[64 * 57];

    const int tid = threadIdx.x;
    const int warp = tid >> 5, lane = tid & 31;
    const int gid = lane >> 2, qid = lane & 3;
    const int m0 = warp * 16;
    const float scale = 0.17677669529663687f;

    for (int t = tid; t < 64 * 33; t += 128) qs[t] = 0.f;
    for (int t = tid; t < 32 * 57; t += 128) kt[t] = 0.f;
    for (int t = tid; t < 56 * 36; t += 128) vs[t] = 0.f;
    __syncthreads();

    const __half* base = qkv + (size_t)win * 49 * (3 * CC);
    for (int t = tid; t < 49 * 16; t += 128) {
        int r = t >> 4, c = (t & 15) * 2;
        float2 qf = __half22float2(*(const __half2*)&base[r * 576 +       head * 32 + c]);
        float2 kf = __half22float2(*(const __half2*)&base[r * 576 + 192 + head * 32 + c]);
        float2 vf = __half22float2(*(const __half2*)&base[r * 576 + 384 + head * 32 + c]);
        qs[r * 33 + c]     = tf32r(qf.x * scale);
        qs[r * 33 + c + 1] = tf32r(qf.y * scale);
        kt[c * 57 + r]       = kf.x;
        kt[(c + 1) * 57 + r] = kf.y;
        vs[r * 36 + c]     = vf.x;
        vs[r * 36 + c + 1] = vf.y;
    }
    __syncthreads();

    {
        float sacc[7][4] = {};
#pragma unroll
        for (int kk = 0; kk < 4; kk++) {
            int k = kk * 8;
            float4 a = make_float4(qs[(m0 + gid) * 33 + k + qid],
                                   qs[(m0 + gid + 8) * 33 + k + qid],
                                   qs[(m0 + gid) * 33 + k + qid + 4],
                                   qs[(m0 + gid + 8) * 33 + k + qid + 4]);
#pragma unroll
            for (int nt = 0; nt < 7; nt++) {
                float b0 = kt[(k + qid) * 57 + nt * 8 + gid];
                float b1 = kt[(k + qid + 4) * 57 + nt * 8 + gid];
                mma8(sacc[nt], a, b0, b1);
            }
        }
#pragma unroll
        for (int nt = 0; nt < 7; nt++) {
            int j = nt * 8 + qid * 2;
            sm[(m0 + gid) * 57 + j]     = sacc[nt][0];
            sm[(m0 + gid) * 57 + j + 1] = sacc[nt][1];
            sm[(m0 + gid + 8) * 57 + j]     = sacc[nt][2];
            sm[(m0 + gid + 8) * 57 + j + 1] = sacc[nt][3];
        }
    }
    __syncthreads();

    const float* mk = mask + (size_t)(win & 63) * 49 * 49;
    for (int r = warp; r < 49; r += 4) {
        float v0 = sm[r * 57 + lane] + mk[r * 49 + lane];
        float v1 = (lane < 17) ? sm[r * 57 + 32 + lane] + mk[r * 49 + 32 + lane] : -1e30f;
        float m = fmaxf(v0, v1);
#pragma unroll
        for (int o = 16; o; o >>= 1) m = fmaxf(m, __shfl_xor_sync(0xffffffffu, m, o));
        float e0 = __expf(v0 - m);
        float e1 = (lane < 17) ? __expf(v1 - m) : 0.f;
        float s = e0 + e1;
#pragma unroll
        for (int o = 16; o; o >>= 1) s += __shfl_xor_sync(0xffffffffu, s, o);
        float inv = 1.f / s;
        sm[r * 57 + lane] = tf32r(e0 * inv);
        if (lane < 17) sm[r * 57 + 32 + lane] = tf32r(e1 * inv);
    }
    __syncthreads();

    {
        float oacc[4][4] = {};
#pragma unroll
        for (int kk = 0; kk < 7; kk++) {
            int k = kk * 8;
            float4 a = make_float4(sm[(m0 + gid) * 57 + k + qid],
                                   sm[(m0 + gid + 8) * 57 + k + qid],
                                   sm[(m0 + gid) * 57 + k + qid + 4],
                                   sm[(m0 + gid + 8) * 57 + k + qid + 4]);
#pragma unroll
            for (int nt = 0; nt < 4; nt++) {
                float b0 = vs[(k + qid) * 36 + nt * 8 + gid];
                float b1 = vs[(k + qid + 4) * 36 + nt * 8 + gid];
                mma8(oacc[nt], a, b0, b1);
            }
        }
        int i0 = m0 + gid, i1 = m0 + gid + 8;
#pragma unroll
        for (int nt = 0; nt < 4; nt++) {
            int d = head * 32 + nt * 8 + qid * 2;
            if (i0 < 49) {
                int r0 = win * 49 + i0;
                *(__half2*)&out[aimg_idx(r0, d, 192)] =
                    __floats2half2_rn(oacc[nt][0], oacc[nt][1]);
            }
            if (i1 < 49) {
                int r1 = win * 49 + i1;
                *(__half2*)&out[aimg_idx(r1, d, 192)] =
                    __floats2half2_rn(oacc[nt][2], oacc[nt][3]);
            }
        }
    }
}

extern "C" void kernel_launch(void* const* d_in, const int* in_sizes, int n_in,
                              void* d_out, int out_size)
{
    const float* x      = (const float*)d_in[0];
    const float* qkv_w  = (const float*)d_in[1];
    const float* qkv_b  = (const float*)d_in[2];
    const float* proj_w = (const float*)d_in[3];
    const float* proj_b = (const float*)d_in[4];
    const float* n1g    = (const float*)d_in[5];
    const float* n1b    = (const float*)d_in[6];
    const float* n2g    = (const float*)d_in[7];
    const float* n2b    = (const float*)d_in[8];
    const float* fc1w   = (const float*)d_in[9];
    const float* fc1b   = (const float*)d_in[10];
    const float* fc2w   = (const float*)d_in[11];
    const float* fc2b   = (const float*)d_in[12];
    const float* amask  = (const float*)d_in[13];
    float* out = (float*)d_out;

    __half *xn, *qkv, *att, *h, *h1, *w;
    float *xr;
    cudaGetSymbolAddress((void**)&xn,  g_xn);
    cudaGetSymbolAddress((void**)&qkv, g_qkv);
    cudaGetSymbolAddress((void**)&att, g_att);
    cudaGetSymbolAddress((void**)&xr,  g_xr);
    cudaGetSymbolAddress((void**)&h,   g_h);
    cudaGetSymbolAddress((void**)&h1,  g_h1);
    cudaGetSymbolAddress((void**)&w,   g_w);

    const int SMEM_GEMM = 40960;   // 32KB A + 8KB B
    cudaFuncSetAttribute(tgemm<0>, cudaFuncAttributeMaxDynamicSharedMemorySize, SMEM_GEMM);
    cudaFuncSetAttribute(tgemm<1>, cudaFuncAttributeMaxDynamicSharedMemorySize, SMEM_GEMM);
    cudaFuncSetAttribute(tgemm<2>, cudaFuncAttributeMaxDynamicSharedMemorySize, SMEM_GEMM);
    cudaFuncSetAttribute(tgemm<3>, cudaFuncAttributeMaxDynamicSharedMemorySize, SMEM_GEMM);

    // 0) build B fragment images (fp16)
    prep_b<<<(110592 + 255) / 256, 256>>>(qkv_w,  w + OFF_QKVW, 192, 576);
    prep_b<<<(36864  + 255) / 256, 256>>>(proj_w, w + OFF_PROJW, 192, 192);
    prep_b<<<(147456 + 255) / 256, 256>>>(fc1w,   w + OFF_FC1W, 192, 768);
    prep_b<<<(147456 + 255) / 256, 256>>>(fc2w,   w + OFF_FC2W, 768, 192);

    dim3 lnb(32, 8);
    // 1) shift + window partition + LN1 -> A-image
    ln_kernel<<<TOK / 8, lnb>>>(x, n1g, n1b, xn, 1);
    // 2) QKV GEMM (100352,192)@(192,576) -> half linear qkv
    tgemm<0><<<dim3(9, 392), 128, SMEM_GEMM>>>(xn, w + OFF_QKVW, qkv_b, qkv, 576, 192, nullptr);
    // 3) windowed attention -> A-image
    attn_kernel<<<NWIN * NHEAD, 128>>>(qkv, amask, att);
    // 4) proj GEMM + un-window/un-shift -> fp32 linear xr
    tgemm<1><<<dim3(3, 392), 128, SMEM_GEMM>>>(att, w + OFF_PROJW, proj_b, xr, 192, 192, nullptr);
    // 5) LN2 -> A-image
    ln_kernel<<<TOK / 8, lnb>>>(xr, n2g, n2b, h, 0);
    // 6) fc1 + exact GELU -> A-image (K=768)
    tgemm<2><<<dim3(12, 392), 128, SMEM_GEMM>>>(h, w + OFF_FC1W, fc1b, h1, 768, 192, nullptr);
    // 7) fc2 + bias + residual -> fp32 out
    tgemm<3><<<dim3(3, 392), 128, SMEM_GEMM>>>(h1, w + OFF_FC2W, fc2b, out, 192, 768, xr);
}

// round 9
// speedup vs baseline: 6.5127x; 1.2472x over previous
#include <cuda_runtime.h>
#include <cuda_fp16.h>
#include <math.h>
#include <stdint.h>

#define TOK   100352          // B*H*W tokens
#define CC    192
#define NHEAD 6
#define HDIM  32
#define NWIN  2048            // B * 64 windows
#define HIDN  768

// Scratch (allocation-free rule: __device__ globals).
__device__ __half g_xn [TOK * CC];        // LN1 out, A-frag image
__device__ __half g_qkv[TOK * 3 * CC];    // qkv, linear half
__device__ __half g_att[TOK * CC];        // attn out, A-frag image
__device__ float  g_xr [TOK * CC];        // residual branch, fp32 linear
__device__ __half g_h  [TOK * CC];        // LN2 out, A-frag image
__device__ __half g_h1 [TOK * HIDN];      // fc1+gelu out, A-frag image
__device__ __half g_w  [442368];          // B-frag images (qkv|proj|fc1|fc2)
__device__ float  g_msk[64 * 49 * 56];    // padded mask [win][r][j56], -1e9 pad

#define OFF_QKVW  0
#define OFF_PROJW 110592
#define OFF_FC1W  147456
#define OFF_FC2W  294912

__device__ __forceinline__ int win_row_to_token(int row) {
    int win = row / 49, n = row % 49;
    int b   = win >> 6, wij = win & 63;
    int wi  = wij >> 3, wj  = wij & 7;
    int hh  = wi * 7 + n / 7;
    int ww  = wj * 7 + n % 7;
    int h = hh + 3; if (h >= 56) h -= 56;
    int w = ww + 3; if (w >= 56) w -= 56;
    return b * 3136 + h * 56 + w;
}

// A-fragment image (half) index for (row, col) of an [*, K] activation (m16n8k16).
__device__ __forceinline__ size_t aimg_idx(int row, int col, int K) {
    int nk  = K >> 5;
    int mb  = row >> 8, m = row & 255;
    int ch  = col >> 5, kin = col & 31;
    int m16 = m >> 4, rr = m & 15;
    int gid = rr & 7, hr = rr >> 3;
    int ks  = kin >> 4, kk = kin & 15;
    int hi  = kk >> 3, q = (kk & 7) >> 1, e = kk & 1;
    int lane = gid * 4 + q;
    int reg  = hi * 2 + hr;
    return ((size_t)mb * nk + ch) * 8192
         + (size_t)((m16 * 2 + ks) * 256 + lane * 8 + reg * 2 + e);
}

// B-fragment image (half) index for weight element (k, n), K the k-dim.
__device__ __forceinline__ size_t bimg_idx(int k, int n, int K) {
    int nk = K >> 5;
    int bx = n >> 6, n64 = n & 63;
    int ch = k >> 5, kin = k & 31;
    int ks = kin >> 4, kk = kin & 15;
    int hi = kk >> 3, q = (kk & 7) >> 1, e = kk & 1;
    int sg = n64 >> 4, ntp = (n64 >> 3) & 1, g = n64 & 7;
    int lane = g * 4 + q;
    return ((size_t)bx * nk + ch) * 2048
         + (size_t)((ks * 4 + sg) * 256 + lane * 8 + ntp * 4 + hi * 2 + e);
}

__device__ __forceinline__ void mma16(float* c, uint4 a, uint32_t b0, uint32_t b1) {
    asm volatile(
        "mma.sync.aligned.m16n8k16.row.col.f32.f16.f16.f32 "
        "{%0,%1,%2,%3},{%4,%5,%6,%7},{%8,%9},{%0,%1,%2,%3};"
        : "+f"(c[0]), "+f"(c[1]), "+f"(c[2]), "+f"(c[3])
        : "r"(a.x), "r"(a.y), "r"(a.z), "r"(a.w), "r"(b0), "r"(b1));
}

// Combined prep: 4 weight B-frag images + padded mask, one launch.
__global__ void prep_all(const float* __restrict__ qkv_w, const float* __restrict__ proj_w,
                         const float* __restrict__ fc1w, const float* __restrict__ fc2w,
                         const float* __restrict__ amask,
                         __half* __restrict__ w, float* __restrict__ msk)
{
    int i = blockIdx.x * 256 + threadIdx.x;
    if (i < 110592) {
        int k = i / 576, n = i % 576;
        w[OFF_QKVW + bimg_idx(k, n, 192)] = __float2half_rn(qkv_w[i]);
    } else if (i < 147456) {
        int j = i - 110592, k = j / 192, n = j % 192;
        w[OFF_PROJW + bimg_idx(k, n, 192)] = __float2half_rn(proj_w[j]);
    } else if (i < 294912) {
        int j = i - 147456, k = j / 768, n = j % 768;
        w[OFF_FC1W + bimg_idx(k, n, 192)] = __float2half_rn(fc1w[j]);
    } else if (i < 442368) {
        int j = i - 294912, k = j / 192, n = j % 192;
        w[OFF_FC2W + bimg_idx(k, n, 768)] = __float2half_rn(fc2w[j]);
    } else if (i < 442368 + 64 * 49 * 56) {
        int j = i - 442368;
        int win = j / 2744, rj = j % 2744, r = rj / 56, jj = rj % 56;
        msk[j] = (jj < 49) ? amask[win * 2401 + r * 49 + jj] : -1e9f;
    }
}

// LayerNorm over C=192, one warp per row; writes half A-frag image.
__global__ void ln_kernel(const float* __restrict__ x, const float* __restrict__ g,
                          const float* __restrict__ bta, __half* __restrict__ out,
                          int permute)
{
    int row  = blockIdx.x * 8 + threadIdx.y;
    int lane = threadIdx.x;
    int src  = permute ? win_row_to_token(row) : row;
    const float* xp = x + (size_t)src * CC;
    float2 v[3];
    float s = 0.f, s2 = 0.f;
#pragma unroll
    for (int i = 0; i < 3; i++) {
        v[i] = *(const float2*)&xp[i * 64 + lane * 2];
        s += v[i].x + v[i].y;
        s2 += v[i].x * v[i].x + v[i].y * v[i].y;
    }
#pragma unroll
    for (int o = 16; o; o >>= 1) {
        s  += __shfl_xor_sync(0xffffffffu, s, o);
        s2 += __shfl_xor_sync(0xffffffffu, s2, o);
    }
    float mu  = s * (1.f / 192.f);
    float var = s2 * (1.f / 192.f) - mu * mu;
    float inv = rsqrtf(var + 1e-5f);
#pragma unroll
    for (int i = 0; i < 3; i++) {
        int c = i * 64 + lane * 2;
        float2 gg = *(const float2*)&g[c];
        float2 bb = *(const float2*)&bta[c];
        float o0 = (v[i].x - mu) * inv * gg.x + bb.x;
        float o1 = (v[i].y - mu) * inv * gg.y + bb.y;
        *(__half2*)&out[aimg_idx(row, c, 192)] = __floats2half2_rn(o0, o1);
    }
}

// FP16 mma.sync GEMM: CTA 256x64, 4 warps stacked in M, warp tile 64x64.
// (unchanged from round 8)
template<int EPI>
__global__ void __launch_bounds__(128)
tgemm(const __half* __restrict__ Aimg, const __half* __restrict__ Bimg,
      const float* __restrict__ bias, void* __restrict__ CoutV,
      int Nn, int K, const float* __restrict__ resid)
{
    extern __shared__ __half dsh[];
    __half* Asm = dsh;                // [2][8192] halves = 32KB
    __half* Bsm = dsh + 2 * 8192;     // [2][2048] halves = 8KB

    const int tid  = threadIdx.x;
    const int warp = tid >> 5, lane = tid & 31;
    const int gid = lane >> 2, qid = lane & 3;
    const int bm = blockIdx.y * 256, bn = blockIdx.x * 64;
    const int nk = K >> 5;

    float acc[4][8][4] = {};

    const uint32_t asmb = (uint32_t)__cvta_generic_to_shared(Asm);
    const uint32_t bsmb = asmb + 32768;
    const __half* Ab = Aimg + (size_t)blockIdx.y * nk * 8192;
    const __half* Bb = Bimg + (size_t)blockIdx.x * nk * 2048;

    auto issue = [&](int c) {
        int st = c & 1;
        const uint4* as = (const uint4*)(Ab + (size_t)c * 8192) + tid;
        uint32_t ad = asmb + (uint32_t)(st * 16384 + tid * 16);
#pragma unroll
        for (int p = 0; p < 8; p++)
            asm volatile("cp.async.cg.shared.global [%0], [%1], 16;"
                         :: "r"(ad + p * 2048), "l"(as + p * 128));
        const uint4* bs = (const uint4*)(Bb + (size_t)c * 2048) + tid;
        uint32_t bd = bsmb + (uint32_t)(st * 4096 + tid * 16);
#pragma unroll
        for (int p = 0; p < 2; p++)
            asm volatile("cp.async.cg.shared.global [%0], [%1], 16;"
                         :: "r"(bd + p * 2048), "l"(bs + p * 128));
        asm volatile("cp.async.commit_group;" ::: "memory");
    };

    issue(0);
    for (int c = 0; c < nk; c++) {
        if (c + 1 < nk) {
            issue(c + 1);
            asm volatile("cp.async.wait_group 1;" ::: "memory");
        } else {
            asm volatile("cp.async.wait_group 0;" ::: "memory");
        }
        __syncthreads();

        const __half* ab = Asm + (c & 1) * 8192;
        const __half* bb = Bsm + (c & 1) * 2048;
#pragma unroll
        for (int ks = 0; ks < 2; ks++) {
            uint4 fa[4], fb[4];
#pragma unroll
            for (int mt = 0; mt < 4; mt++)
                fa[mt] = *(const uint4*)&ab[((warp * 4 + mt) * 2 + ks) * 256 + lane * 8];
#pragma unroll
            for (int s = 0; s < 4; s++)
                fb[s] = *(const uint4*)&bb[(ks * 4 + s) * 256 + lane * 8];
#pragma unroll
            for (int mt = 0; mt < 4; mt++)
#pragma unroll
                for (int s = 0; s < 4; s++) {
                    mma16(acc[mt][s * 2],     fa[mt], fb[s].x, fb[s].y);
                    mma16(acc[mt][s * 2 + 1], fa[mt], fb[s].z, fb[s].w);
                }
        }
        __syncthreads();
    }

#pragma unroll
    for (int mt = 0; mt < 4; mt++) {
#pragma unroll
        for (int hf = 0; hf < 2; hf++) {
            int row  = bm + warp * 64 + mt * 16 + gid + hf * 8;
            int orow = (EPI == 1) ? win_row_to_token(row) : row;
#pragma unroll
            for (int nt = 0; nt < 8; nt++) {
                int col = bn + nt * 8 + qid * 2;
                float v0 = acc[mt][nt][hf * 2 + 0] + bias[col];
                float v1 = acc[mt][nt][hf * 2 + 1] + bias[col + 1];
                if (EPI == 0) {
                    __half* O = (__half*)CoutV;
                    *(__half2*)&O[(size_t)row * Nn + col] = __floats2half2_rn(v0, v1);
                } else if (EPI == 1) {
                    float* O = (float*)CoutV;
                    *(float2*)&O[(size_t)orow * Nn + col] = make_float2(v0, v1);
                } else if (EPI == 2) {
                    v0 = 0.5f * v0 * (1.f + erff(v0 * 0.70710678118654752f));
                    v1 = 0.5f * v1 * (1.f + erff(v1 * 0.70710678118654752f));
                    __half* O = (__half*)CoutV;
                    *(__half2*)&O[aimg_idx(row, col, 768)] = __floats2half2_rn(v0, v1);
                } else {
                    float* O = (float*)CoutV;
                    float r0 = resid[(size_t)row * CC + col];
                    float r1 = resid[(size_t)row * CC + col + 1];
                    *(float2*)&O[(size_t)row * Nn + col] = make_float2(v0 + r0, v1 + r1);
                }
            }
        }
    }
}

// FP16 tensor-core attention: one CTA per (window, head), 4 warps.
// S = (Q*scale) K^T + mask; in-register softmax (quad shuffles); O = P V.
// No inter-warp dependencies after the load sync.
__global__ void __launch_bounds__(128)
attn_kernel(const __half* __restrict__ qkv, const float* __restrict__ mask2,
            __half* __restrict__ out)
{
    int win  = blockIdx.x / NHEAD;
    int head = blockIdx.x % NHEAD;
    __shared__ __half qa[2048];        // Q A-frag image: 4 m16 x 2 ks x 256
    __shared__ __half kt[56 * 40];     // K [j][d], stride 40 (bank-clean B frags)
    __shared__ __half vt[32 * 72];     // V^T [d][j], stride 72, j padded to 64
    __shared__ __half pim[4096];       // P A-frag image: 4 m16 x 4 ks x 256

    const int tid = threadIdx.x;
    const int warp = tid >> 5, lane = tid & 31;
    const int gid = lane >> 2, qid = lane & 3;
    const float scale = 0.17677669529663687f;

    // zero-fill (pad regions must be 0; smem garbage could encode NaN)
    {
        uint32_t* z;
        z = (uint32_t*)qa;  for (int t = tid; t < 1024; t += 128) z[t] = 0;
        z = (uint32_t*)kt;  for (int t = tid; t < 1120; t += 128) z[t] = 0;
        z = (uint32_t*)vt;  for (int t = tid; t < 1152; t += 128) z[t] = 0;
        z = (uint32_t*)pim; for (int t = tid; t < 2048; t += 128) z[t] = 0;
    }
    __syncthreads();

    const __half* base = qkv + (size_t)win * 49 * 576;
    for (int t = tid; t < 49 * 16; t += 128) {
        int r = t >> 4, c = (t & 15) * 2;
        __half2 qh = *(const __half2*)&base[r * 576 +       head * 32 + c];
        __half2 kh = *(const __half2*)&base[r * 576 + 192 + head * 32 + c];
        __half2 vh = *(const __half2*)&base[r * 576 + 384 + head * 32 + c];
        float2 qf = __half22float2(qh);
        // Q into A-frag image (rr<16 since r<49 -> m16 tile r>>4)
        int m16 = r >> 4, rr = r & 15;
        int ks = c >> 4, kk = c & 15;
        int ln = (rr & 7) * 4 + ((kk & 7) >> 1);
        int reg = (kk >> 3) * 2 + (rr >> 3);
        *(__half2*)&qa[(m16 * 2 + ks) * 256 + ln * 8 + reg * 2] =
            __floats2half2_rn(qf.x * scale, qf.y * scale);
        *(__half2*)&kt[r * 40 + c] = kh;
        vt[c * 72 + r]       = vh.x;
        vt[(c + 1) * 72 + r] = vh.y;
    }
    __syncthreads();

    // S = Q K^T : warp rows [warp*16, +16), n tiles j=0..55, k=32
    float sacc[7][4] = {};
#pragma unroll
    for (int ks = 0; ks < 2; ks++) {
        uint4 fa = *(const uint4*)&qa[(warp * 2 + ks) * 256 + lane * 8];
#pragma unroll
        for (int nt = 0; nt < 7; nt++) {
            uint32_t b0 = *(const uint32_t*)&kt[(nt * 8 + gid) * 40 + ks * 16 + qid * 2];
            uint32_t b1 = *(const uint32_t*)&kt[(nt * 8 + gid) * 40 + ks * 16 + 8 + qid * 2];
            mma16(sacc[nt], fa, b0, b1);
        }
    }

    // In-register masked softmax per row half (quad = same row).
    const float* msk = mask2 + (size_t)(win & 63) * 2744;
#pragma unroll
    for (int hf = 0; hf < 2; hf++) {
        int r = warp * 16 + hf * 8 + gid;
        bool ok = (r < 49);
        float v[14];
#pragma unroll
        for (int nt = 0; nt < 7; nt++) {
            float2 mk = ok ? *(const float2*)&msk[r * 56 + nt * 8 + qid * 2]
                           : make_float2(-1e9f, -1e9f);
            v[nt * 2]     = sacc[nt][hf * 2]     + mk.x;
            v[nt * 2 + 1] = sacc[nt][hf * 2 + 1] + mk.y;
        }
        float m = v[0];
#pragma unroll
        for (int i = 1; i < 14; i++) m = fmaxf(m, v[i]);
        m = fmaxf(m, __shfl_xor_sync(0xffffffffu, m, 1));
        m = fmaxf(m, __shfl_xor_sync(0xffffffffu, m, 2));
        float s = 0.f;
#pragma unroll
        for (int i = 0; i < 14; i++) { v[i] = __expf(v[i] - m); s += v[i]; }
        s += __shfl_xor_sync(0xffffffffu, s, 1);
        s += __shfl_xor_sync(0xffffffffu, s, 2);
        float inv = 1.f / s;
        // write P frags: lane-identity into pim (j=nt*8+2q -> ks=nt>>1, slot (nt&1)*4+hf*2)
#pragma unroll
        for (int nt = 0; nt < 7; nt++) {
            *(__half2*)&pim[(warp * 4 + (nt >> 1)) * 256 + lane * 8 + (nt & 1) * 4 + hf * 2] =
                __floats2half2_rn(v[nt * 2] * inv, v[nt * 2 + 1] * inv);
        }
    }

    // O = P V : k = 64 (j padded), n = 32
    float oacc[4][4] = {};
#pragma unroll
    for (int ks = 0; ks < 4; ks++) {
        uint4 fa = *(const uint4*)&pim[(warp * 4 + ks) * 256 + lane * 8];
#pragma unroll
        for (int nt = 0; nt < 4; nt++) {
            uint32_t b0 = *(const uint32_t*)&vt[(nt * 8 + gid) * 72 + ks * 16 + qid * 2];
            uint32_t b1 = *(const uint32_t*)&vt[(nt * 8 + gid) * 72 + ks * 16 + 8 + qid * 2];
            mma16(oacc[nt], fa, b0, b1);
        }
    }

    int i0 = warp * 16 + gid, i1 = warp * 16 + 8 + gid;
#pragma unroll
    for (int nt = 0; nt < 4; nt++) {
        int d = head * 32 + nt * 8 + qid * 2;
        if (i0 < 49) {
            int r0 = win * 49 + i0;
            *(__half2*)&out[aimg_idx(r0, d, 192)] =
                __floats2half2_rn(oacc[nt][0], oacc[nt][1]);
        }
        if (i1 < 49) {
            int r1 = win * 49 + i1;
            *(__half2*)&out[aimg_idx(r1, d, 192)] =
                __floats2half2_rn(oacc[nt][2], oacc[nt][3]);
        }
    }
}

extern "C" void kernel_launch(void* const* d_in, const int* in_sizes, int n_in,
                              void* d_out, int out_size)
{
    const float* x      = (const float*)d_in[0];
    const float* qkv_w  = (const float*)d_in[1];
    const float* qkv_b  = (const float*)d_in[2];
    const float* proj_w = (const float*)d_in[3];
    const float* proj_b = (const float*)d_in[4];
    const float* n1g    = (const float*)d_in[5];
    const float* n1b    = (const float*)d_in[6];
    const float* n2g    = (const float*)d_in[7];
    const float* n2b    = (const float*)d_in[8];
    const float* fc1w   = (const float*)d_in[9];
    const float* fc1b   = (const float*)d_in[10];
    const float* fc2w   = (const float*)d_in[11];
    const float* fc2b   = (const float*)d_in[12];
    const float* amask  = (const float*)d_in[13];
    float* out = (float*)d_out;

    __half *xn, *qkv, *att, *h, *h1, *w;
    float *xr, *msk;
    cudaGetSymbolAddress((void**)&xn,  g_xn);
    cudaGetSymbolAddress((void**)&qkv, g_qkv);
    cudaGetSymbolAddress((void**)&att, g_att);
    cudaGetSymbolAddress((void**)&xr,  g_xr);
    cudaGetSymbolAddress((void**)&h,   g_h);
    cudaGetSymbolAddress((void**)&h1,  g_h1);
    cudaGetSymbolAddress((void**)&w,   g_w);
    cudaGetSymbolAddress((void**)&msk, g_msk);

    const int SMEM_GEMM = 40960;   // 32KB A + 8KB B
    cudaFuncSetAttribute(tgemm<0>, cudaFuncAttributeMaxDynamicSharedMemorySize, SMEM_GEMM);
    cudaFuncSetAttribute(tgemm<1>, cudaFuncAttributeMaxDynamicSharedMemorySize, SMEM_GEMM);
    cudaFuncSetAttribute(tgemm<2>, cudaFuncAttributeMaxDynamicSharedMemorySize, SMEM_GEMM);
    cudaFuncSetAttribute(tgemm<3>, cudaFuncAttributeMaxDynamicSharedMemorySize, SMEM_GEMM);

    // 0) build B fragment images + padded mask (one launch)
    prep_all<<<(442368 + 64 * 49 * 56 + 255) / 256, 256>>>(
        qkv_w, proj_w, fc1w, fc2w, amask, w, msk);

    dim3 lnb(32, 8);
    // 1) shift + window partition + LN1 -> A-image
    ln_kernel<<<TOK / 8, lnb>>>(x, n1g, n1b, xn, 1);
    // 2) QKV GEMM (100352,192)@(192,576) -> half linear qkv
    tgemm<0><<<dim3(9, 392), 128, SMEM_GEMM>>>(xn, w + OFF_QKVW, qkv_b, qkv, 576, 192, nullptr);
    // 3) windowed attention -> A-image
    attn_kernel<<<NWIN * NHEAD, 128>>>(qkv, msk, att);
    // 4) proj GEMM + un-window/un-shift -> fp32 linear xr
    tgemm<1><<<dim3(3, 392), 128, SMEM_GEMM>>>(att, w + OFF_PROJW, proj_b, xr, 192, 192, nullptr);
    // 5) LN2 -> A-image
    ln_kernel<<<TOK / 8, lnb>>>(xr, n2g, n2b, h, 0);
    // 6) fc1 + exact GELU -> A-image (K=768)
    tgemm<2><<<dim3(12, 392), 128, SMEM_GEMM>>>(h, w + OFF_FC1W, fc1b, h1, 768, 192, nullptr);
    // 7) fc2 + bias + residual -> fp32 out
    tgemm<3><<<dim3(3, 392), 128, SMEM_GEMM>>>(h1, w + OFF_FC2W, fc2b, out, 192, 768, xr);
}